// round 1
// baseline (speedup 1.0000x reference)
#include <cuda_runtime.h>

#define B_    2048
#define N_    38
#define E_    4
#define DIN_  9
#define H0_   256
#define H1_   256
#define L0_   512
#define NE_   152           // E_*N_
#define ROWS_ 77824         // B_*N_

// ---------------- device scratch (static, no allocation) ----------------
__device__ float g_h0 [(size_t)ROWS_ * H0_];        // pre-BN layer0 output
__device__ float g_hs1[(size_t)ROWS_ * H1_];        // self term layer1
__device__ float g_m1 [(size_t)ROWS_ * H1_ * E_];   // edge messages layer1
__device__ float g_h1 [(size_t)ROWS_ * H1_];        // pre-BN layer1 output
__device__ float g_h2 [(size_t)ROWS_ * L0_];        // pre-BN linear output
__device__ float g_sum  [3][N_];
__device__ float g_ssq  [3][N_];
__device__ float g_scale[3][N_];
__device__ float g_shift[3][N_];

// ---------------- zero the stat accumulators ----------------
__global__ void k_zero() {
    int i = threadIdx.x;
    if (i < 3 * N_) {
        (&g_sum[0][0])[i] = 0.f;
        (&g_ssq[0][0])[i] = 0.f;
    }
}

// ---------------- layer 0: fused gconv (per-b CTA, 32-col chunk) ----------------
// h0[b,m,c] = bs[c] + sum_k xs[m,k]*Ws[c,k] + sum_{e,n} adj[b,e,m,n]*M[n,c,e]
// where M[n,c,e] = be[c*4+e] + sum_k xs[n,k]*We[(c*4+e),k],  xs = MASK*x
__global__ __launch_bounds__(256) void k_layer0(
    const float* __restrict__ adj, const float* __restrict__ x,
    const float* __restrict__ Ws,  const float* __restrict__ bs,
    const float* __restrict__ We,  const float* __restrict__ be)
{
    __shared__ float adjT[40][153];   // [m][e*38+n], padded rows 38..39
    __shared__ float Ms[NE_][33];     // [e*38+n][c-chunk]
    __shared__ float xs[40][12];
    const int b   = blockIdx.x;
    const int cc  = blockIdx.y * 32;
    const int tid = threadIdx.x;

    for (int i = tid; i < N_ * DIN_; i += 256) {
        int n = i / DIN_, k = i % DIN_;
        xs[n][k] = (n & 1) ? x[(b * N_ + n) * DIN_ + k] : 0.f;  // MASK: even rows zero
    }
    const float* adjb = adj + (size_t)b * (E_ * N_ * N_);
    for (int i = tid; i < E_ * N_ * N_; i += 256) {
        int e = i / (N_ * N_); int r = i % (N_ * N_);
        adjT[r / N_][e * N_ + (r % N_)] = adjb[i];
    }
    __syncthreads();

    for (int i = tid; i < NE_ * 32; i += 256) {
        int row = i >> 5, col = i & 31;
        int e = row / N_, n = row % N_;
        int wr = (cc + col) * E_ + e;
        const float* wrow = We + wr * DIN_;
        float a = be[wr];
#pragma unroll
        for (int k = 0; k < DIN_; k++) a = fmaf(xs[n][k], wrow[k], a);
        Ms[row][col] = a;
    }
    __syncthreads();

    const int w = tid >> 5, lane = tid & 31;
    const int c = cc + lane;
    const float* wsr = Ws + c * DIN_;
    const float bsv = bs[c];
    float acc[5];
#pragma unroll
    for (int mi = 0; mi < 5; mi++) {
        int m = w + mi * 8;
        if (m < N_) {
            float a = bsv;
#pragma unroll
            for (int k = 0; k < DIN_; k++) a = fmaf(xs[m][k], wsr[k], a);
            acc[mi] = a;
        } else acc[mi] = 0.f;
    }
    for (int j = 0; j < NE_; j++) {
        float mv = Ms[j][lane];
#pragma unroll
        for (int mi = 0; mi < 5; mi++)
            acc[mi] = fmaf(adjT[w + mi * 8][j], mv, acc[mi]);
    }
#pragma unroll
    for (int mi = 0; mi < 5; mi++) {
        int m = w + mi * 8;
        if (m < N_) {
            float v = acc[mi];
            g_h0[(size_t)(b * N_ + m) * H0_ + c] = v;
            float s = v, q = v * v;
#pragma unroll
            for (int o = 16; o; o >>= 1) {
                s += __shfl_xor_sync(~0u, s, o);
                q += __shfl_xor_sync(~0u, q, o);
            }
            if (lane == 0) { atomicAdd(&g_sum[0][m], s); atomicAdd(&g_ssq[0][m], q); }
        }
    }
}

// ---------------- BN stat finalize: (scale, shift) per node ----------------
__global__ void k_finalize(const float* __restrict__ gg, const float* __restrict__ bb,
                           float inv_count, int layer)
{
    int t = threadIdx.x;
    if (t < N_) {
        float mu  = g_sum[layer][t] * inv_count;
        float var = g_ssq[layer][t] * inv_count - mu * mu;
        float sc  = gg[t] * rsqrtf(var + 1e-5f);
        g_scale[layer][t] = sc;
        g_shift[layer][t] = bb[t] - mu * sc;
    }
}

// ---------------- layer 1 big GEMM: [hs1 | m1] = bnrelu0(h0) @ [Ws1;We1]^T + bias ----------------
__global__ __launch_bounds__(256) void k_gemm1(
    const float* __restrict__ Ws, const float* __restrict__ We,
    const float* __restrict__ bs, const float* __restrict__ be)
{
    __shared__ float As[16][68];
    __shared__ float Bs[16][68];
    const int tid = threadIdx.x;
    const int ty = tid >> 4, tx = tid & 15;
    const int rb = blockIdx.y * 64;
    const int cb = blockIdx.x * 64;     // 0..1279, block either all <256 or all >=256

    const int arow = tid >> 2;
    const int ak   = (tid & 3) * 4;
    const int ag   = rb + arow;
    const int an   = ag % N_;
    const float asc = g_scale[0][an], ash = g_shift[0][an];
    const float* Ap = g_h0 + (size_t)ag * H0_ + ak;
    const int jg = cb + arow;
    const float* Bp = (jg < H1_ ? Ws + (size_t)jg * H0_
                                : We + (size_t)(jg - H1_) * H0_) + ak;

    float acc[4][4] = {};
    for (int kt = 0; kt < H0_; kt += 16) {
        float4 av = *(const float4*)(Ap + kt);
        float4 bv = *(const float4*)(Bp + kt);
        av.x = fmaxf(fmaf(av.x, asc, ash), 0.f);
        av.y = fmaxf(fmaf(av.y, asc, ash), 0.f);
        av.z = fmaxf(fmaf(av.z, asc, ash), 0.f);
        av.w = fmaxf(fmaf(av.w, asc, ash), 0.f);
        As[ak + 0][arow] = av.x; As[ak + 1][arow] = av.y;
        As[ak + 2][arow] = av.z; As[ak + 3][arow] = av.w;
        Bs[ak + 0][arow] = bv.x; Bs[ak + 1][arow] = bv.y;
        Bs[ak + 2][arow] = bv.z; Bs[ak + 3][arow] = bv.w;
        __syncthreads();
#pragma unroll
        for (int k = 0; k < 16; k++) {
            float4 a = *(const float4*)&As[k][ty * 4];
            float4 bq = *(const float4*)&Bs[k][tx * 4];
            acc[0][0] = fmaf(a.x, bq.x, acc[0][0]); acc[0][1] = fmaf(a.x, bq.y, acc[0][1]);
            acc[0][2] = fmaf(a.x, bq.z, acc[0][2]); acc[0][3] = fmaf(a.x, bq.w, acc[0][3]);
            acc[1][0] = fmaf(a.y, bq.x, acc[1][0]); acc[1][1] = fmaf(a.y, bq.y, acc[1][1]);
            acc[1][2] = fmaf(a.y, bq.z, acc[1][2]); acc[1][3] = fmaf(a.y, bq.w, acc[1][3]);
            acc[2][0] = fmaf(a.z, bq.x, acc[2][0]); acc[2][1] = fmaf(a.z, bq.y, acc[2][1]);
            acc[2][2] = fmaf(a.z, bq.z, acc[2][2]); acc[2][3] = fmaf(a.z, bq.w, acc[2][3]);
            acc[3][0] = fmaf(a.w, bq.x, acc[3][0]); acc[3][1] = fmaf(a.w, bq.y, acc[3][1]);
            acc[3][2] = fmaf(a.w, bq.z, acc[3][2]); acc[3][3] = fmaf(a.w, bq.w, acc[3][3]);
        }
        __syncthreads();
    }
    const int c0 = cb + tx * 4;
    float4 bias4 = (cb < H1_) ? *(const float4*)(bs + c0)
                              : *(const float4*)(be + (c0 - H1_));
#pragma unroll
    for (int i = 0; i < 4; i++) {
        int r = rb + ty * 4 + i;
        float4 v = make_float4(acc[i][0] + bias4.x, acc[i][1] + bias4.y,
                               acc[i][2] + bias4.z, acc[i][3] + bias4.w);
        if (cb < H1_) *(float4*)&g_hs1[(size_t)r * H1_ + c0] = v;
        else          *(float4*)&g_m1 [(size_t)r * (H1_ * E_) + (c0 - H1_)] = v;
    }
}

// ---------------- layer 1 einsum: h1 = hs1 + adj-contract(m1), + stats ----------------
__global__ __launch_bounds__(256) void k_einsum1(const float* __restrict__ adj)
{
    __shared__ float adjT[40][153];
    __shared__ float Ms[NE_][33];
    const int b   = blockIdx.x;
    const int cc  = blockIdx.y * 32;
    const int tid = threadIdx.x;

    const float* adjb = adj + (size_t)b * (E_ * N_ * N_);
    for (int i = tid; i < E_ * N_ * N_; i += 256) {
        int e = i / (N_ * N_); int r = i % (N_ * N_);
        adjT[r / N_][e * N_ + (r % N_)] = adjb[i];
    }
    for (int i = tid; i < NE_ * 32; i += 256) {
        int e = i & 3, col = (i >> 2) & 31, n = i >> 7;
        Ms[e * N_ + n][col] =
            g_m1[(size_t)(b * N_ + n) * (H1_ * E_) + (cc + col) * E_ + e];
    }
    __syncthreads();

    const int w = tid >> 5, lane = tid & 31;
    const int c = cc + lane;
    float acc[5];
#pragma unroll
    for (int mi = 0; mi < 5; mi++) {
        int m = w + mi * 8;
        acc[mi] = (m < N_) ? g_hs1[(size_t)(b * N_ + m) * H1_ + c] : 0.f;
    }
    for (int j = 0; j < NE_; j++) {
        float mv = Ms[j][lane];
#pragma unroll
        for (int mi = 0; mi < 5; mi++)
            acc[mi] = fmaf(adjT[w + mi * 8][j], mv, acc[mi]);
    }
#pragma unroll
    for (int mi = 0; mi < 5; mi++) {
        int m = w + mi * 8;
        if (m < N_) {
            float v = acc[mi];
            g_h1[(size_t)(b * N_ + m) * H1_ + c] = v;
            float s = v, q = v * v;
#pragma unroll
            for (int o = 16; o; o >>= 1) {
                s += __shfl_xor_sync(~0u, s, o);
                q += __shfl_xor_sync(~0u, q, o);
            }
            if (lane == 0) { atomicAdd(&g_sum[1][m], s); atomicAdd(&g_ssq[1][m], q); }
        }
    }
}

// ---------------- linear layer: h2 = bnrelu1(h1) @ lW0^T + lb0, n-major grid + stats ----------------
__global__ __launch_bounds__(256) void k_gemm2(
    const float* __restrict__ W, const float* __restrict__ bias)
{
    __shared__ float As[16][68];
    __shared__ float Bs[16][68];
    __shared__ float rs[8], rq[8];
    const int tid = threadIdx.x;
    const int ty = tid >> 4, tx = tid & 15;
    const int bb = blockIdx.y * 64;   // batch base
    const int cb = blockIdx.x * 64;   // column base (<512)
    const int nn = blockIdx.z;        // node index

    const int arow = tid >> 2;
    const int ak   = (tid & 3) * 4;
    const float asc = g_scale[1][nn], ash = g_shift[1][nn];
    const float* Ap = g_h1 + (size_t)((bb + arow) * N_ + nn) * H1_ + ak;
    const float* Bp = W + (size_t)(cb + arow) * H1_ + ak;

    float acc[4][4] = {};
    for (int kt = 0; kt < H1_; kt += 16) {
        float4 av = *(const float4*)(Ap + kt);
        float4 bv = *(const float4*)(Bp + kt);
        av.x = fmaxf(fmaf(av.x, asc, ash), 0.f);
        av.y = fmaxf(fmaf(av.y, asc, ash), 0.f);
        av.z = fmaxf(fmaf(av.z, asc, ash), 0.f);
        av.w = fmaxf(fmaf(av.w, asc, ash), 0.f);
        As[ak + 0][arow] = av.x; As[ak + 1][arow] = av.y;
        As[ak + 2][arow] = av.z; As[ak + 3][arow] = av.w;
        Bs[ak + 0][arow] = bv.x; Bs[ak + 1][arow] = bv.y;
        Bs[ak + 2][arow] = bv.z; Bs[ak + 3][arow] = bv.w;
        __syncthreads();
#pragma unroll
        for (int k = 0; k < 16; k++) {
            float4 a = *(const float4*)&As[k][ty * 4];
            float4 bq = *(const float4*)&Bs[k][tx * 4];
            acc[0][0] = fmaf(a.x, bq.x, acc[0][0]); acc[0][1] = fmaf(a.x, bq.y, acc[0][1]);
            acc[0][2] = fmaf(a.x, bq.z, acc[0][2]); acc[0][3] = fmaf(a.x, bq.w, acc[0][3]);
            acc[1][0] = fmaf(a.y, bq.x, acc[1][0]); acc[1][1] = fmaf(a.y, bq.y, acc[1][1]);
            acc[1][2] = fmaf(a.y, bq.z, acc[1][2]); acc[1][3] = fmaf(a.y, bq.w, acc[1][3]);
            acc[2][0] = fmaf(a.z, bq.x, acc[2][0]); acc[2][1] = fmaf(a.z, bq.y, acc[2][1]);
            acc[2][2] = fmaf(a.z, bq.z, acc[2][2]); acc[2][3] = fmaf(a.z, bq.w, acc[2][3]);
            acc[3][0] = fmaf(a.w, bq.x, acc[3][0]); acc[3][1] = fmaf(a.w, bq.y, acc[3][1]);
            acc[3][2] = fmaf(a.w, bq.z, acc[3][2]); acc[3][3] = fmaf(a.w, bq.w, acc[3][3]);
        }
        __syncthreads();
    }
    const int c0 = cb + tx * 4;
    float4 bias4 = *(const float4*)(bias + c0);
    float s = 0.f, q = 0.f;
#pragma unroll
    for (int i = 0; i < 4; i++) {
        int r = (bb + ty * 4 + i) * N_ + nn;
        float4 v = make_float4(acc[i][0] + bias4.x, acc[i][1] + bias4.y,
                               acc[i][2] + bias4.z, acc[i][3] + bias4.w);
        *(float4*)&g_h2[(size_t)r * L0_ + c0] = v;
        s += v.x + v.y + v.z + v.w;
        q += v.x * v.x + v.y * v.y + v.z * v.z + v.w * v.w;
    }
#pragma unroll
    for (int o = 16; o; o >>= 1) {
        s += __shfl_xor_sync(~0u, s, o);
        q += __shfl_xor_sync(~0u, q, o);
    }
    if ((tid & 31) == 0) { rs[tid >> 5] = s; rq[tid >> 5] = q; }
    __syncthreads();
    if (tid == 0) {
        float S = 0.f, Q = 0.f;
#pragma unroll
        for (int i = 0; i < 8; i++) { S += rs[i]; Q += rq[i]; }
        atomicAdd(&g_sum[2][nn], S); atomicAdd(&g_ssq[2][nn], Q);
    }
}

// ---------------- final: f = bnrelu2(h2) @ fW^T + fb; coupling output + logdet ----------------
__global__ __launch_bounds__(256) void k_final(
    const float* __restrict__ x, const float* __restrict__ fW,
    const float* __restrict__ fb, float* __restrict__ out, float* __restrict__ logdet)
{
    __shared__ float fws[2 * DIN_][L0_];   // 36 KB
    __shared__ float ld;
    const int b   = blockIdx.x;
    const int tid = threadIdx.x;
    for (int i = tid; i < 2 * DIN_ * L0_; i += 256)
        fws[i / L0_][i % L0_] = fW[i];
    if (tid == 0) ld = 0.f;
    __syncthreads();
    const int w = tid >> 5, lane = tid & 31;
    for (int n = w; n < N_; n += 8) {
        const float* hr = g_h2 + (size_t)(b * N_ + n) * L0_;
        const float sc = g_scale[2][n], sh = g_shift[2][n];
        float acc[18];
#pragma unroll
        for (int j = 0; j < 18; j++) acc[j] = 0.f;
        for (int kk = 0; kk < L0_ / 32; kk++) {
            int k = lane + kk * 32;
            float a = fmaxf(fmaf(hr[k], sc, sh), 0.f);
#pragma unroll
            for (int j = 0; j < 18; j++) acc[j] = fmaf(a, fws[j][k], acc[j]);
        }
#pragma unroll
        for (int j = 0; j < 18; j++) {
#pragma unroll
            for (int o = 16; o; o >>= 1) acc[j] += __shfl_xor_sync(~0u, acc[j], o);
        }
        if (lane < DIN_) {
            int d = lane;
            float sl = acc[d] + fb[d];
            float tv = acc[DIN_ + d] + fb[DIN_ + d];
            float sg = 1.f / (1.f + __expf(-sl));
            float xv = x[(b * N_ + n) * DIN_ + d];
            // even n: masked (mask=0) -> (x+t)*s ; odd n: passthrough x
            out[(size_t)(b * N_ + n) * DIN_ + d] = (n & 1) ? xv : (xv + tv) * sg;
            float ls = fminf(sl, 0.f) - log1pf(__expf(-fabsf(sl)));
            atomicAdd(&ld, ls);
        }
    }
    __syncthreads();
    if (tid == 0) logdet[b] = ld;
}

// ---------------- launch ----------------
extern "C" void kernel_launch(void* const* d_in, const int* in_sizes, int n_in,
                              void* d_out, int out_size)
{
    const float* adj  = (const float*)d_in[0];
    const float* x    = (const float*)d_in[1];
    const float* cWs0 = (const float*)d_in[2];
    const float* cbs0 = (const float*)d_in[3];
    const float* cWe0 = (const float*)d_in[4];
    const float* cbe0 = (const float*)d_in[5];
    const float* cg0  = (const float*)d_in[6];
    const float* cb0  = (const float*)d_in[7];
    const float* cWs1 = (const float*)d_in[8];
    const float* cbs1 = (const float*)d_in[9];
    const float* cWe1 = (const float*)d_in[10];
    const float* cbe1 = (const float*)d_in[11];
    const float* cg1  = (const float*)d_in[12];
    const float* cb1  = (const float*)d_in[13];
    const float* lW0  = (const float*)d_in[14];
    const float* lb0  = (const float*)d_in[15];
    const float* lg0  = (const float*)d_in[16];
    const float* lbb0 = (const float*)d_in[17];
    const float* fW   = (const float*)d_in[18];
    const float* fb   = (const float*)d_in[19];
    float* out    = (float*)d_out;
    float* logdet = out + (size_t)B_ * N_ * DIN_;

    k_zero<<<1, 256>>>();
    k_layer0<<<dim3(B_, 8), 256>>>(adj, x, cWs0, cbs0, cWe0, cbe0);
    k_finalize<<<1, 64>>>(cg0, cb0, 1.f / ((float)B_ * H0_), 0);
    k_gemm1<<<dim3(20, ROWS_ / 64), 256>>>(cWs1, cWe1, cbs1, cbe1);
    k_einsum1<<<dim3(B_, 8), 256>>>(adj);
    k_finalize<<<1, 64>>>(cg1, cb1, 1.f / ((float)B_ * H1_), 1);
    k_gemm2<<<dim3(L0_ / 64, B_ / 64, N_), 256>>>(lW0, lb0);
    k_finalize<<<1, 64>>>(lg0, lbb0, 1.f / ((float)B_ * L0_), 2);
    k_final<<<B_, 256>>>(x, fW, fb, out, logdet);
}

// round 2
// speedup vs baseline: 1.9373x; 1.9373x over previous
#include <cuda_runtime.h>
#include <cstdint>

#define B_    2048
#define N_    38
#define E_    4
#define DIN_  9
#define H0_   256
#define H1_   256
#define L0_   512
#define NE_   152           // E_*N_
#define ROWS_ 77824         // B_*N_
#define KF_   64            // padded K for layer0 feature GEMM

// ---------------- device scratch (static, no allocation) ----------------
__device__ float g_F  [(size_t)ROWS_ * KF_];        // layer0 features [P | xs | rowsum | pad]
__device__ float g_W0c[H0_ * KF_];                  // combined layer0 weights
__device__ float g_h0 [(size_t)ROWS_ * H0_];        // pre-BN layer0 output
__device__ float g_hs1[(size_t)ROWS_ * H1_];        // self term layer1
__device__ float g_m1 [(size_t)ROWS_ * H1_ * E_];   // edge messages layer1
__device__ float g_h1 [(size_t)ROWS_ * H1_];        // pre-BN layer1 output
__device__ float g_h2 [(size_t)ROWS_ * L0_];        // pre-BN linear output
__device__ float g_sum  [3][N_];
__device__ float g_ssq  [3][N_];
__device__ float g_scale[3][N_];
__device__ float g_shift[3][N_];

// ---------------- helpers ----------------
__device__ __forceinline__ float tf32r(float x) {
    uint32_t u;
    asm("cvt.rna.tf32.f32 %0, %1;" : "=r"(u) : "f"(x));
    return __uint_as_float(u);
}

__device__ __forceinline__ void mma8(float* c, const uint32_t* a, const uint32_t* b) {
    asm volatile(
        "mma.sync.aligned.m16n8k8.row.col.f32.tf32.tf32.f32 "
        "{%0,%1,%2,%3},{%4,%5,%6,%7},{%8,%9},{%0,%1,%2,%3};"
        : "+f"(c[0]), "+f"(c[1]), "+f"(c[2]), "+f"(c[3])
        : "r"(a[0]), "r"(a[1]), "r"(a[2]), "r"(a[3]), "r"(b[0]), "r"(b[1]));
}

// ---------------- zero the stat accumulators ----------------
__global__ void k_zero() {
    int i = threadIdx.x;
    if (i < 3 * N_) {
        (&g_sum[0][0])[i] = 0.f;
        (&g_ssq[0][0])[i] = 0.f;
    }
}

// ---------------- build combined layer0 weight matrix ----------------
// W0c[c][e*9+k] = We0[(c*4+e)*9+k]; [c][36+k] = Ws0[c*9+k]; [c][45+e] = be0[c*4+e]; rest 0
__global__ void k_prep(const float* __restrict__ Ws, const float* __restrict__ We,
                       const float* __restrict__ be)
{
    int i = blockIdx.x * 256 + threadIdx.x;
    if (i < H0_ * KF_) {
        int row = i >> 6, c = i & 63;
        float v = 0.f;
        if (c < 36) { int e = c / 9, k = c - e * 9; v = We[(row * 4 + e) * 9 + k]; }
        else if (c < 45) v = Ws[row * 9 + (c - 36)];
        else if (c < 49) v = be[row * 4 + (c - 45)];
        g_W0c[i] = v;
    }
}

// ---------------- build layer0 features: F = [P(36) | xs(9) | rowsum(4) | 0...] ----------------
// P[b,m,e*9+k] = sum_n adj[b,e,m,n] * xs[b,n,k],   xs = MASK*x
__global__ __launch_bounds__(256) void k_feat(const float* __restrict__ adj,
                                              const float* __restrict__ x)
{
    __shared__ float adjS[NE_][40];   // [e*38+m][n]
    __shared__ float xsS[N_][9];
    const int b = blockIdx.x, tid = threadIdx.x;
    const float* adjb = adj + (size_t)b * (E_ * N_ * N_);
    for (int i = tid; i < E_ * N_ * N_; i += 256) adjS[i / N_][i % N_] = adjb[i];
    for (int i = tid; i < N_ * 9; i += 256) {
        int n = i / 9, k = i - n * 9;
        xsS[n][k] = (n & 1) ? x[(b * N_ + n) * 9 + k] : 0.f;   // MASK: even rows zero
    }
    __syncthreads();
    for (int i = tid; i < N_ * KF_; i += 256) {
        int m = i >> 6, c = i & 63;
        float v = 0.f;
        if (c < 36) {
            int e = c / 9, k = c - e * 9;
            const float* ar = adjS[e * N_ + m];
#pragma unroll
            for (int n = 0; n < N_; n++) v = fmaf(ar[n], xsS[n][k], v);
        } else if (c < 45) {
            v = xsS[m][c - 36];
        } else if (c < 49) {
            const float* ar = adjS[(c - 45) * N_ + m];
#pragma unroll
            for (int n = 0; n < N_; n++) v += ar[n];
        }
        g_F[((size_t)b * N_ + m) * KF_ + c] = v;
    }
}

// ---------------- unified tf32 MMA GEMM, 128x128 CTA tile, 256 threads ----------------
// MODE 0: h0  = F(77824xKF) @ W0c^T + bs0                (grid 2 x 608)
// MODE 1: [hs1|m1] = bnrelu0(h0) @ [Ws1;We1]^T + bias    (grid 10 x 608)
// MODE 2: h2  = bnrelu1(h1[:,nn,:]) @ lW0^T + lb0 +stats (grid 4 x 16 x 38)
template<int MODE>
__global__ __launch_bounds__(256, 2) void k_mma(
    const float* __restrict__ Bw, const float* __restrict__ Bw2,
    const float* __restrict__ bias, const float* __restrict__ bias2)
{
    constexpr int KTOT = (MODE == 0) ? KF_ : 256;
    __shared__ float As[32][136];
    __shared__ float Bs[32][136];
    __shared__ float red[16];
    const int tid  = threadIdx.x;
    const int lane = tid & 31, wid = tid >> 5;
    const int wm = wid & 1, wn = wid >> 1;
    const int g = lane >> 2, tig = lane & 3;
    const int rb = blockIdx.y * 128;
    const int cb = blockIdx.x * 128;
    const int nn = (MODE == 2) ? blockIdx.z : 0;

    // staging roles: quad q covers 16 contiguous floats per row piece
    const int q  = tid & 3;
    const int r0 = tid >> 2;      // 0..63; rows r0 and r0+64

    const float* Ap[2]; float sc[2], sh[2];
    const float* Bp[2];
#pragma unroll
    for (int rr = 0; rr < 2; rr++) {
        int r = r0 + rr * 64;
        if (MODE == 0) {
            Ap[rr] = g_F + (size_t)(rb + r) * KF_;
            sc[rr] = 1.f; sh[rr] = 0.f;
        } else if (MODE == 1) {
            int grow = rb + r;
            int n = grow % N_;
            Ap[rr] = g_h0 + (size_t)grow * 256;
            sc[rr] = g_scale[0][n]; sh[rr] = g_shift[0][n];
        } else {
            int b = rb + r;
            Ap[rr] = g_h1 + ((size_t)b * N_ + nn) * 256;
            sc[rr] = g_scale[1][nn]; sh[rr] = g_shift[1][nn];
        }
        int nrow = cb + r0 + rr * 64;
        if (MODE == 0)      Bp[rr] = g_W0c + (size_t)nrow * KF_;
        else if (MODE == 1) Bp[rr] = (nrow < 256) ? (Bw + (size_t)nrow * 256)
                                                  : (Bw2 + (size_t)(nrow - 256) * 256);
        else                Bp[rr] = Bw + (size_t)nrow * 256;
    }

    float acc[4][4][4];
#pragma unroll
    for (int a = 0; a < 4; a++)
#pragma unroll
        for (int b2 = 0; b2 < 4; b2++)
#pragma unroll
            for (int c2 = 0; c2 < 4; c2++) acc[a][b2][c2] = 0.f;

    for (int kt = 0; kt < KTOT; kt += 32) {
#pragma unroll
        for (int rr = 0; rr < 2; rr++) {
#pragma unroll
            for (int j = 0; j < 2; j++) {
                const int k0 = q * 4 + j * 16;
                float4 v = *(const float4*)(Ap[rr] + kt + k0);
                float vv[4] = {v.x, v.y, v.z, v.w};
#pragma unroll
                for (int s2 = 0; s2 < 4; s2++) {
                    float t = vv[s2];
                    if (MODE != 0) t = fmaxf(fmaf(t, sc[rr], sh[rr]), 0.f);
                    vv[s2] = tf32r(t);
                }
#pragma unroll
                for (int s2 = 0; s2 < 4; s2++) {     // swizzled order: conflict-free
                    int i = (s2 + q) & 3;
                    As[k0 + i][r0 + rr * 64] = vv[i];
                }
                float4 w = *(const float4*)(Bp[rr] + kt + k0);
                float ww[4] = {w.x, w.y, w.z, w.w};
#pragma unroll
                for (int s2 = 0; s2 < 4; s2++) ww[s2] = tf32r(ww[s2]);
#pragma unroll
                for (int s2 = 0; s2 < 4; s2++) {
                    int i = (s2 + q) & 3;
                    Bs[k0 + i][r0 + rr * 64] = ww[i];
                }
            }
        }
        __syncthreads();
#pragma unroll
        for (int kk = 0; kk < 32; kk += 8) {
            uint32_t af[4][4], bf[4][2];
#pragma unroll
            for (int mt = 0; mt < 4; mt++) {
                int m = wm * 64 + mt * 16 + g;
                af[mt][0] = __float_as_uint(As[kk + tig    ][m]);
                af[mt][1] = __float_as_uint(As[kk + tig    ][m + 8]);
                af[mt][2] = __float_as_uint(As[kk + tig + 4][m]);
                af[mt][3] = __float_as_uint(As[kk + tig + 4][m + 8]);
            }
#pragma unroll
            for (int nt = 0; nt < 4; nt++) {
                int n = wn * 32 + nt * 8 + g;
                bf[nt][0] = __float_as_uint(Bs[kk + tig    ][n]);
                bf[nt][1] = __float_as_uint(Bs[kk + tig + 4][n]);
            }
#pragma unroll
            for (int mt = 0; mt < 4; mt++)
#pragma unroll
                for (int nt = 0; nt < 4; nt++)
                    mma8(acc[mt][nt], af[mt], bf[nt]);
        }
        __syncthreads();
    }

    // ---- epilogue ----
    float s = 0.f, qs = 0.f;   // MODE 2 stats
#pragma unroll
    for (int mt = 0; mt < 4; mt++) {
        const int rloc = wm * 64 + mt * 16 + g;
#pragma unroll
        for (int nt = 0; nt < 4; nt++) {
            const int col = cb + wn * 32 + nt * 8 + tig * 2;
            float b0, b1;
            if (MODE == 1 && cb >= 256) { b0 = bias2[col - 256]; b1 = bias2[col - 255]; }
            else                        { b0 = bias[col];        b1 = bias[col + 1];    }
            float2 v0 = make_float2(acc[mt][nt][0] + b0, acc[mt][nt][1] + b1);
            float2 v1 = make_float2(acc[mt][nt][2] + b0, acc[mt][nt][3] + b1);
            if (MODE == 0) {
                int row = rb + rloc;
                *(float2*)&g_h0[(size_t)row * 256 + col]       = v0;
                *(float2*)&g_h0[(size_t)(row + 8) * 256 + col] = v1;
            } else if (MODE == 1) {
                int row = rb + rloc;
                if (cb < 256) {
                    *(float2*)&g_hs1[(size_t)row * 256 + col]       = v0;
                    *(float2*)&g_hs1[(size_t)(row + 8) * 256 + col] = v1;
                } else {
                    *(float2*)&g_m1[(size_t)row * 1024 + col - 256]       = v0;
                    *(float2*)&g_m1[(size_t)(row + 8) * 1024 + col - 256] = v1;
                }
            } else {
                size_t row0 = ((size_t)(rb + rloc) * N_ + nn) * L0_;
                size_t row1 = ((size_t)(rb + rloc + 8) * N_ + nn) * L0_;
                *(float2*)&g_h2[row0 + col] = v0;
                *(float2*)&g_h2[row1 + col] = v1;
                s  += v0.x + v0.y + v1.x + v1.y;
                qs += v0.x * v0.x + v0.y * v0.y + v1.x * v1.x + v1.y * v1.y;
            }
        }
    }
    if (MODE == 2) {
#pragma unroll
        for (int o = 16; o; o >>= 1) {
            s  += __shfl_xor_sync(~0u, s, o);
            qs += __shfl_xor_sync(~0u, qs, o);
        }
        if (lane == 0) { red[wid] = s; red[wid + 8] = qs; }
        __syncthreads();
        if (tid == 0) {
            float S = 0.f, Q = 0.f;
#pragma unroll
            for (int i = 0; i < 8; i++) { S += red[i]; Q += red[i + 8]; }
            atomicAdd(&g_sum[2][nn], S);
            atomicAdd(&g_ssq[2][nn], Q);
        }
    }
}

// ---------------- layer0 stats (read h0) ----------------
__global__ __launch_bounds__(256) void k_stats0() {
    const int row  = blockIdx.x * 8 + (threadIdx.x >> 5);
    const int lane = threadIdx.x & 31;
    const float* p = g_h0 + (size_t)row * 256;
    float s = 0.f, q = 0.f;
#pragma unroll
    for (int i = 0; i < 8; i++) { float v = p[lane + i * 32]; s += v; q += v * v; }
#pragma unroll
    for (int o = 16; o; o >>= 1) {
        s += __shfl_xor_sync(~0u, s, o);
        q += __shfl_xor_sync(~0u, q, o);
    }
    if (lane == 0) {
        int n = row % N_;
        atomicAdd(&g_sum[0][n], s);
        atomicAdd(&g_ssq[0][n], q);
    }
}

// ---------------- BN stat finalize ----------------
__global__ void k_finalize(const float* __restrict__ gg, const float* __restrict__ bb,
                           float inv_count, int layer)
{
    int t = threadIdx.x;
    if (t < N_) {
        float mu  = g_sum[layer][t] * inv_count;
        float var = g_ssq[layer][t] * inv_count - mu * mu;
        float scv = gg[t] * rsqrtf(var + 1e-5f);
        g_scale[layer][t] = scv;
        g_shift[layer][t] = bb[t] - mu * scv;
    }
}

// ---------------- layer 1 einsum: h1 = hs1 + adj-contract(m1), + stats ----------------
__global__ __launch_bounds__(256) void k_einsum1(const float* __restrict__ adj)
{
    extern __shared__ float smr[];
    float (*adjT)[153] = (float(*)[153])smr;              // 40 x 153
    float (*Ms)[66]    = (float(*)[66])(smr + 40 * 153);  // 152 x 66
    const int b = blockIdx.x, cc = blockIdx.y * 64, tid = threadIdx.x;

    const float* adjb = adj + (size_t)b * (E_ * N_ * N_);
    for (int i = tid; i < E_ * N_ * N_; i += 256) {
        int e = i / (N_ * N_); int r = i % (N_ * N_);
        adjT[r / N_][e * N_ + (r % N_)] = adjb[i];
    }
    for (int i = tid; i < N_ * 64; i += 256) {
        int n = i >> 6, col = i & 63;
        float4 v = *(const float4*)&g_m1[((size_t)(b * N_ + n)) * 1024 + (size_t)(cc + col) * 4];
        Ms[n][col] = v.x; Ms[N_ + n][col] = v.y; Ms[2 * N_ + n][col] = v.z; Ms[3 * N_ + n][col] = v.w;
    }
    __syncthreads();

    const int w = tid >> 5, lane = tid & 31;
    const int c = cc + lane;
    float acc[5][2];
#pragma unroll
    for (int mi = 0; mi < 5; mi++) {
        int m = w + mi * 8;
        if (m < N_) {
            acc[mi][0] = g_hs1[((size_t)(b * N_ + m)) * 256 + c];
            acc[mi][1] = g_hs1[((size_t)(b * N_ + m)) * 256 + c + 32];
        } else acc[mi][0] = acc[mi][1] = 0.f;
    }
    for (int j = 0; j < NE_; j++) {
        float mv0 = Ms[j][lane], mv1 = Ms[j][lane + 32];
#pragma unroll
        for (int mi = 0; mi < 5; mi++) {
            float av = adjT[w + mi * 8][j];
            acc[mi][0] = fmaf(av, mv0, acc[mi][0]);
            acc[mi][1] = fmaf(av, mv1, acc[mi][1]);
        }
    }
#pragma unroll
    for (int mi = 0; mi < 5; mi++) {
        int m = w + mi * 8;
        if (m < N_) {
#pragma unroll
            for (int h = 0; h < 2; h++) {
                float v = acc[mi][h];
                g_h1[((size_t)(b * N_ + m)) * 256 + c + h * 32] = v;
                float s = v, qq = v * v;
#pragma unroll
                for (int o = 16; o; o >>= 1) {
                    s  += __shfl_xor_sync(~0u, s, o);
                    qq += __shfl_xor_sync(~0u, qq, o);
                }
                if (lane == 0) { atomicAdd(&g_sum[1][m], s); atomicAdd(&g_ssq[1][m], qq); }
            }
        }
    }
}

// ---------------- final: f = bnrelu2(h2) @ fW^T + fb; coupling output + logdet ----------------
__global__ __launch_bounds__(256) void k_final(
    const float* __restrict__ x, const float* __restrict__ fW,
    const float* __restrict__ fb, float* __restrict__ out, float* __restrict__ logdet)
{
    __shared__ float fws[2 * DIN_][L0_];   // 36 KB
    __shared__ float ld;
    const int b   = blockIdx.x;
    const int tid = threadIdx.x;
    for (int i = tid; i < 2 * DIN_ * L0_; i += 256)
        fws[i / L0_][i % L0_] = fW[i];
    if (tid == 0) ld = 0.f;
    __syncthreads();
    const int w = tid >> 5, lane = tid & 31;
    for (int n = w; n < N_; n += 8) {
        const float* hr = g_h2 + (size_t)(b * N_ + n) * L0_;
        const float scv = g_scale[2][n], shv = g_shift[2][n];
        float acc[18];
#pragma unroll
        for (int j = 0; j < 18; j++) acc[j] = 0.f;
        for (int kk = 0; kk < L0_ / 32; kk++) {
            int k = lane + kk * 32;
            float a = fmaxf(fmaf(hr[k], scv, shv), 0.f);
#pragma unroll
            for (int j = 0; j < 18; j++) acc[j] = fmaf(a, fws[j][k], acc[j]);
        }
#pragma unroll
        for (int j = 0; j < 18; j++) {
#pragma unroll
            for (int o = 16; o; o >>= 1) acc[j] += __shfl_xor_sync(~0u, acc[j], o);
        }
        if (lane < DIN_) {
            int d = lane;
            float sl = acc[d] + fb[d];
            float tv = acc[DIN_ + d] + fb[DIN_ + d];
            float sg = 1.f / (1.f + __expf(-sl));
            float xv = x[(b * N_ + n) * DIN_ + d];
            out[(size_t)(b * N_ + n) * DIN_ + d] = (n & 1) ? xv : (xv + tv) * sg;
            float ls = fminf(sl, 0.f) - log1pf(__expf(-fabsf(sl)));
            atomicAdd(&ld, ls);
        }
    }
    __syncthreads();
    if (tid == 0) logdet[b] = ld;
}

// ---------------- launch ----------------
extern "C" void kernel_launch(void* const* d_in, const int* in_sizes, int n_in,
                              void* d_out, int out_size)
{
    const float* adj  = (const float*)d_in[0];
    const float* x    = (const float*)d_in[1];
    const float* cWs0 = (const float*)d_in[2];
    const float* cbs0 = (const float*)d_in[3];
    const float* cWe0 = (const float*)d_in[4];
    const float* cbe0 = (const float*)d_in[5];
    const float* cg0  = (const float*)d_in[6];
    const float* cb0  = (const float*)d_in[7];
    const float* cWs1 = (const float*)d_in[8];
    const float* cbs1 = (const float*)d_in[9];
    const float* cWe1 = (const float*)d_in[10];
    const float* cbe1 = (const float*)d_in[11];
    const float* cg1  = (const float*)d_in[12];
    const float* cb1  = (const float*)d_in[13];
    const float* lW0  = (const float*)d_in[14];
    const float* lb0  = (const float*)d_in[15];
    const float* lg0  = (const float*)d_in[16];
    const float* lbb0 = (const float*)d_in[17];
    const float* fW   = (const float*)d_in[18];
    const float* fb   = (const float*)d_in[19];
    float* out    = (float*)d_out;
    float* logdet = out + (size_t)B_ * N_ * DIN_;

    static bool attr_set = false;
    (void)attr_set;
    cudaFuncSetAttribute(k_einsum1, cudaFuncAttributeMaxDynamicSharedMemorySize, 65536);
    const int einsum_smem = (40 * 153 + NE_ * 66) * 4;

    k_zero<<<1, 256>>>();
    k_prep<<<(H0_ * KF_ + 255) / 256, 256>>>(cWs0, cWe0, cbe0);
    k_feat<<<B_, 256>>>(adj, x);
    k_mma<0><<<dim3(H0_ / 128, ROWS_ / 128), 256>>>(nullptr, nullptr, cbs0, nullptr);
    k_stats0<<<ROWS_ / 8, 256>>>();
    k_finalize<<<1, 64>>>(cg0, cb0, 1.f / ((float)B_ * H0_), 0);
    k_mma<1><<<dim3(1280 / 128, ROWS_ / 128), 256>>>(cWs1, cWe1, cbs1, cbe1);
    k_einsum1<<<dim3(B_, 4), 256, einsum_smem>>>(adj);
    k_finalize<<<1, 64>>>(cg1, cb1, 1.f / ((float)B_ * H1_), 1);
    k_mma<2><<<dim3(L0_ / 128, B_ / 128, N_), 256>>>(lW0, nullptr, lb0, nullptr);
    k_finalize<<<1, 64>>>(lg0, lbb0, 1.f / ((float)B_ * L0_), 2);
    k_final<<<B_, 256>>>(x, fW, fb, out, logdet);
}

// round 5
// speedup vs baseline: 2.0746x; 1.0708x over previous
#include <cuda_runtime.h>
#include <cuda_fp16.h>
#include <cstdint>

#define B_    2048
#define N_    38
#define E_    4
#define DIN_  9
#define H0_   256
#define H1_   256
#define L0_   512
#define NE_   152           // E_*N_
#define ROWS_ 77824         // B_*N_
#define KF_   64            // padded K for layer0 feature GEMM

// ---------------- device scratch (static, no allocation) ----------------
__device__ float g_F  [(size_t)ROWS_ * KF_];        // layer0 features [P | xs | rowsum | pad]
__device__ float g_W0c[H0_ * KF_];                  // combined layer0 weights
__device__ float g_fWp[32 * L0_];                   // padded final weights (18 real rows)
__device__ float g_h0 [(size_t)ROWS_ * H0_];        // pre-BN layer0 output
__device__ float g_hs1[(size_t)ROWS_ * H1_];        // self term layer1
__device__ float g_m1 [(size_t)ROWS_ * H1_ * E_];   // edge messages layer1
__device__ float g_h1 [(size_t)ROWS_ * H1_];        // pre-BN layer1 output
__device__ float g_h2 [(size_t)ROWS_ * L0_];        // pre-BN linear output
__device__ float g_sum  [3][N_];
__device__ float g_ssq  [3][N_];
__device__ float g_scale[3][N_];
__device__ float g_shift[3][N_];

// ---------------- helpers ----------------
__device__ __forceinline__ void mma16(float* c, const uint32_t* a, const uint32_t* b) {
    asm volatile(
        "mma.sync.aligned.m16n8k16.row.col.f32.f16.f16.f32 "
        "{%0,%1,%2,%3},{%4,%5,%6,%7},{%8,%9},{%0,%1,%2,%3};"
        : "+f"(c[0]), "+f"(c[1]), "+f"(c[2]), "+f"(c[3])
        : "r"(a[0]), "r"(a[1]), "r"(a[2]), "r"(a[3]), "r"(b[0]), "r"(b[1]));
}

// ---------------- zero stats + logdet ----------------
__global__ void k_zero(float* __restrict__ logdet) {
    int i = blockIdx.x * 256 + threadIdx.x;
    if (i < 3 * N_) {
        (&g_sum[0][0])[i] = 0.f;
        (&g_ssq[0][0])[i] = 0.f;
    }
    if (i < B_) logdet[i] = 0.f;
}

// ---------------- build combined layer0 weights + padded final weights ----------------
__global__ void k_prep(const float* __restrict__ Ws, const float* __restrict__ We,
                       const float* __restrict__ be, const float* __restrict__ fW)
{
    int i = blockIdx.x * 256 + threadIdx.x;
    if (i < H0_ * KF_) {
        int row = i >> 6, c = i & 63;
        float v = 0.f;
        if (c < 36) { int e = c / 9, k = c - e * 9; v = We[(row * 4 + e) * 9 + k]; }
        else if (c < 45) v = Ws[row * 9 + (c - 36)];
        else if (c < 49) v = be[row * 4 + (c - 45)];
        g_W0c[i] = v;
    } else {
        int j = i - H0_ * KF_;
        if (j < 32 * L0_) {
            int row = j >> 9;
            g_fWp[j] = (row < 18) ? fW[j] : 0.f;
        }
    }
}

// ---------------- build layer0 features: F = [P(36) | xs(9) | rowsum(4) | 0...] ----------------
__global__ __launch_bounds__(256) void k_feat(const float* __restrict__ adj,
                                              const float* __restrict__ x)
{
    __shared__ float adjS[NE_][40];   // [e*38+m][n]
    __shared__ float xsS[N_][9];
    const int b = blockIdx.x, tid = threadIdx.x;
    const float* adjb = adj + (size_t)b * (E_ * N_ * N_);
    for (int i = tid; i < E_ * N_ * N_; i += 256) adjS[i / N_][i % N_] = adjb[i];
    for (int i = tid; i < N_ * 9; i += 256) {
        int n = i / 9, k = i - n * 9;
        xsS[n][k] = (n & 1) ? x[(b * N_ + n) * 9 + k] : 0.f;   // MASK: even rows zero
    }
    __syncthreads();
    for (int i = tid; i < N_ * KF_; i += 256) {
        int m = i >> 6, c = i & 63;
        float v = 0.f;
        if (c < 36) {
            int e = c / 9, k = c - e * 9;
            const float* ar = adjS[e * N_ + m];
#pragma unroll
            for (int n = 0; n < N_; n++) v = fmaf(ar[n], xsS[n][k], v);
        } else if (c < 45) {
            v = xsS[m][c - 36];
        } else if (c < 49) {
            const float* ar = adjS[(c - 45) * N_ + m];
#pragma unroll
            for (int n = 0; n < N_; n++) v += ar[n];
        }
        g_F[((size_t)b * N_ + m) * KF_ + c] = v;
    }
}

// ---------------- unified fp16 MMA GEMM, 128-row CTA tile, 256 threads ----------------
// MODE 0: h0 = F @ W0c^T + bs0                          grid(2, 608)   NT=128 K=64
// MODE 1: [hs1|m1] = bnrelu0(h0) @ [Ws1;We1]^T + bias   grid(10, 608)  NT=128 K=256
// MODE 2: h2 = bnrelu1(h1[:,nn,:]) @ lW0^T + lb0 +stats grid(4,16,38)  NT=128 K=256
// MODE 3: f = bnrelu2(h2) @ fWp^T + fb; coupling+logdet grid(1, 608)   NT=32  K=512
template<int MODE>
__global__ __launch_bounds__(256, 2) void k_mma(
    const float* __restrict__ Bw, const float* __restrict__ Bw2,
    const float* __restrict__ bias, const float* __restrict__ bias2,
    const float* __restrict__ x, float* __restrict__ out, float* __restrict__ logdet)
{
    constexpr int KTOT = (MODE == 0) ? 64 : (MODE == 3) ? 512 : 256;
    constexpr int NT   = (MODE == 3) ? 32 : 128;
    constexpr int MT   = (NT == 128) ? 4 : 1;       // m16 tiles per warp
    constexpr int BPAD = (NT == 128) ? 137 : 41;    // odd strides: conflict-free halves
    constexpr int LAYER = (MODE == 1) ? 0 : (MODE == 2) ? 1 : 2;

    __shared__ __align__(16) half2 As2[32][137];
    __shared__ __align__(16) half2 Bs2[32][BPAD];
    __shared__ float red[16];
    __shared__ float dump[(MODE == 3) ? 128 * 33 : 1];

    const int tid  = threadIdx.x;
    const int wid  = tid >> 5, lane = tid & 31;
    const int g    = lane >> 2, tig = lane & 3;
    const int cb   = blockIdx.x * NT;
    const int rb   = blockIdx.y * 128;
    const int nn   = (MODE == 2) ? blockIdx.z : 0;
    const int WROW = (NT == 128) ? (wid & 1) * 64 : wid * 16;
    const int WCOL = (NT == 128) ? (wid >> 1) * 32 : 0;

    // ---- staging assignment: thread -> (row, k-half) ----
    const int mrow = tid >> 1;
    const int kh   = tid & 1;
    const float* Ap; float asc = 1.f, ash = 0.f;
    {
        const int gr = rb + mrow;
        if (MODE == 0)      Ap = g_F  + (size_t)gr * 64;
        else if (MODE == 1) Ap = g_h0 + (size_t)gr * 256;
        else if (MODE == 2) Ap = g_h1 + ((size_t)gr * N_ + nn) * 256;
        else                Ap = g_h2 + (size_t)gr * 512;
        if (MODE != 0) {
            const int n = (MODE == 2) ? nn : (gr % N_);
            asc = g_scale[LAYER][n]; ash = g_shift[LAYER][n];
        }
    }
    const float* Bp = nullptr;
    if (tid < NT * 2) {
        const int nglob = cb + mrow;
        if (MODE == 0)      Bp = g_W0c + (size_t)nglob * 64;
        else if (MODE == 1) Bp = (nglob < 256) ? (Bw + (size_t)nglob * 256)
                                               : (Bw2 + (size_t)(nglob - 256) * 256);
        else if (MODE == 2) Bp = Bw + (size_t)nglob * 256;
        else                Bp = g_fWp + (size_t)mrow * 512;
    }

    float acc[MT][4][4];
#pragma unroll
    for (int a = 0; a < MT; a++)
#pragma unroll
        for (int b2 = 0; b2 < 4; b2++)
#pragma unroll
            for (int c2 = 0; c2 < 4; c2++) acc[a][b2][c2] = 0.f;

    for (int kt = 0; kt < KTOT; kt += 64) {
        __syncthreads();
        // ---- stage A (BN+ReLU fused, fp32 -> half2) ----
#pragma unroll
        for (int j = 0; j < 8; j++) {
            float4 v = *(const float4*)(Ap + kt + kh * 32 + j * 4);
            if (MODE != 0) {
                v.x = fmaxf(fmaf(v.x, asc, ash), 0.f);
                v.y = fmaxf(fmaf(v.y, asc, ash), 0.f);
                v.z = fmaxf(fmaf(v.z, asc, ash), 0.f);
                v.w = fmaxf(fmaf(v.w, asc, ash), 0.f);
            }
            const int k2 = kh * 16 + j * 2;
            As2[k2][mrow]     = __floats2half2_rn(v.x, v.y);
            As2[k2 + 1][mrow] = __floats2half2_rn(v.z, v.w);
        }
        // ---- stage B ----
        if (tid < NT * 2) {
#pragma unroll
            for (int j = 0; j < 8; j++) {
                float4 w = *(const float4*)(Bp + kt + kh * 32 + j * 4);
                const int k2 = kh * 16 + j * 2;
                Bs2[k2][mrow]     = __floats2half2_rn(w.x, w.y);
                Bs2[k2 + 1][mrow] = __floats2half2_rn(w.z, w.w);
            }
        }
        __syncthreads();
        // ---- 4 x k16 steps ----
#pragma unroll
        for (int kk = 0; kk < 4; kk++) {
            uint32_t af[MT][4], bf[4][2];
#pragma unroll
            for (int mt = 0; mt < MT; mt++) {
                const int m0 = WROW + mt * 16 + g;
                af[mt][0] = *(const uint32_t*)&As2[kk * 8 + tig][m0];
                af[mt][1] = *(const uint32_t*)&As2[kk * 8 + tig][m0 + 8];
                af[mt][2] = *(const uint32_t*)&As2[kk * 8 + tig + 4][m0];
                af[mt][3] = *(const uint32_t*)&As2[kk * 8 + tig + 4][m0 + 8];
            }
#pragma unroll
            for (int nt = 0; nt < 4; nt++) {
                const int n0 = WCOL + nt * 8 + g;
                bf[nt][0] = *(const uint32_t*)&Bs2[kk * 8 + tig][n0];
                bf[nt][1] = *(const uint32_t*)&Bs2[kk * 8 + tig + 4][n0];
            }
#pragma unroll
            for (int mt = 0; mt < MT; mt++)
#pragma unroll
                for (int nt = 0; nt < 4; nt++)
                    mma16(acc[mt][nt], af[mt], bf[nt]);
        }
    }

    // ---- epilogue ----
    if (MODE == 3) {
#pragma unroll
        for (int nt = 0; nt < 4; nt++) {
            const int c = nt * 8 + tig * 2;
            dump[(WROW + g) * 33 + c]     = acc[0][nt][0];
            dump[(WROW + g) * 33 + c + 1] = acc[0][nt][1];
            dump[(WROW + g + 8) * 33 + c]     = acc[0][nt][2];
            dump[(WROW + g + 8) * 33 + c + 1] = acc[0][nt][3];
        }
        __syncthreads();
        const int row = tid >> 1, part = tid & 1;
        const int grow = rb + row;
        const int b = grow / N_, n = grow % N_;
        const int d0 = part * 5, d1 = part ? 9 : 5;
        float lds = 0.f;
        for (int d = d0; d < d1; d++) {
            float sl = dump[row * 33 + d] + bias[d];
            float tv = dump[row * 33 + 9 + d] + bias[9 + d];
            float sg = 1.f / (1.f + __expf(-sl));
            float xv = x[(size_t)grow * DIN_ + d];
            out[(size_t)grow * DIN_ + d] = (n & 1) ? xv : (xv + tv) * sg;
            lds += fminf(sl, 0.f) - log1pf(__expf(-fabsf(sl)));
        }
        atomicAdd(&logdet[b], lds);
        return;
    }

    float s_acc = 0.f, q_acc = 0.f;
#pragma unroll
    for (int mt = 0; mt < MT; mt++) {
        const int rloc = WROW + mt * 16 + g;
#pragma unroll
        for (int nt = 0; nt < 4; nt++) {
            const int col = cb + WCOL + nt * 8 + tig * 2;
            float b0, b1;
            if (MODE == 1 && cb >= 256) { b0 = bias2[col - 256]; b1 = bias2[col - 255]; }
            else                        { b0 = bias[col];        b1 = bias[col + 1];    }
            float2 v0 = make_float2(acc[mt][nt][0] + b0, acc[mt][nt][1] + b1);
            float2 v1 = make_float2(acc[mt][nt][2] + b0, acc[mt][nt][3] + b1);
            if (MODE == 2) {
                s_acc += v0.x + v0.y + v1.x + v1.y;
                q_acc += v0.x * v0.x + v0.y * v0.y + v1.x * v1.x + v1.y * v1.y;
            }
            const int row = rb + rloc;
            if (MODE == 0) {
                *(float2*)&g_h0[(size_t)row * 256 + col]       = v0;
                *(float2*)&g_h0[(size_t)(row + 8) * 256 + col] = v1;
            } else if (MODE == 1) {
                if (cb < 256) {
                    *(float2*)&g_hs1[(size_t)row * 256 + col]       = v0;
                    *(float2*)&g_hs1[(size_t)(row + 8) * 256 + col] = v1;
                } else {
                    *(float2*)&g_m1[(size_t)row * 1024 + col - 256]       = v0;
                    *(float2*)&g_m1[(size_t)(row + 8) * 1024 + col - 256] = v1;
                }
            } else {
                *(float2*)&g_h2[((size_t)row * N_ + nn) * 512 + col]       = v0;
                *(float2*)&g_h2[((size_t)(row + 8) * N_ + nn) * 512 + col] = v1;
            }
        }
    }
    if (MODE == 2) {
#pragma unroll
        for (int o = 16; o; o >>= 1) {
            s_acc += __shfl_xor_sync(~0u, s_acc, o);
            q_acc += __shfl_xor_sync(~0u, q_acc, o);
        }
        if (lane == 0) { red[wid] = s_acc; red[wid + 8] = q_acc; }
        __syncthreads();
        if (tid == 0) {
            float S = 0.f, Q = 0.f;
#pragma unroll
            for (int i = 0; i < 8; i++) { S += red[i]; Q += red[i + 8]; }
            atomicAdd(&g_sum[2][nn], S);
            atomicAdd(&g_ssq[2][nn], Q);
        }
    }
}

// ---------------- layer0 stats (read h0) ----------------
__global__ __launch_bounds__(256) void k_stats0() {
    const int row  = blockIdx.x * 8 + (threadIdx.x >> 5);
    const int lane = threadIdx.x & 31;
    const float* p = g_h0 + (size_t)row * 256;
    float s = 0.f, q = 0.f;
#pragma unroll
    for (int i = 0; i < 8; i++) { float v = p[lane + i * 32]; s += v; q += v * v; }
#pragma unroll
    for (int o = 16; o; o >>= 1) {
        s += __shfl_xor_sync(~0u, s, o);
        q += __shfl_xor_sync(~0u, q, o);
    }
    if (lane == 0) {
        int n = row % N_;
        atomicAdd(&g_sum[0][n], s);
        atomicAdd(&g_ssq[0][n], q);
    }
}

// ---------------- BN stat finalize ----------------
__global__ void k_finalize(const float* __restrict__ gg, const float* __restrict__ bb,
                           float inv_count, int layer)
{
    int t = threadIdx.x;
    if (t < N_) {
        float mu  = g_sum[layer][t] * inv_count;
        float var = g_ssq[layer][t] * inv_count - mu * mu;
        float scv = gg[t] * rsqrtf(var + 1e-5f);
        g_scale[layer][t] = scv;
        g_shift[layer][t] = bb[t] - mu * scv;
    }
}

// ---------------- layer 1 einsum: h1 = hs1 + adj-contract(m1), + stats ----------------
__global__ __launch_bounds__(256) void k_einsum1(const float* __restrict__ adj)
{
    extern __shared__ float smr[];
    float (*adjT)[153] = (float(*)[153])smr;              // 40 x 153
    float (*Ms)[66]    = (float(*)[66])(smr + 40 * 153);  // 152 x 66
    const int b = blockIdx.x, cc = blockIdx.y * 64, tid = threadIdx.x;

    const float* adjb = adj + (size_t)b * (E_ * N_ * N_);
    for (int i = tid; i < E_ * N_ * N_; i += 256) {
        int e = i / (N_ * N_); int r = i % (N_ * N_);
        adjT[r / N_][e * N_ + (r % N_)] = adjb[i];
    }
    for (int i = tid; i < N_ * 64; i += 256) {
        int n = i >> 6, col = i & 63;
        float4 v = *(const float4*)&g_m1[((size_t)(b * N_ + n)) * 1024 + (size_t)(cc + col) * 4];
        Ms[n][col] = v.x; Ms[N_ + n][col] = v.y; Ms[2 * N_ + n][col] = v.z; Ms[3 * N_ + n][col] = v.w;
    }
    __syncthreads();

    const int w = tid >> 5, lane = tid & 31;
    const int c = cc + lane;
    float acc[5][2];
#pragma unroll
    for (int mi = 0; mi < 5; mi++) {
        int m = w + mi * 8;
        if (m < N_) {
            acc[mi][0] = g_hs1[((size_t)(b * N_ + m)) * 256 + c];
            acc[mi][1] = g_hs1[((size_t)(b * N_ + m)) * 256 + c + 32];
        } else acc[mi][0] = acc[mi][1] = 0.f;
    }
    for (int j = 0; j < NE_; j++) {
        float mv0 = Ms[j][lane], mv1 = Ms[j][lane + 32];
#pragma unroll
        for (int mi = 0; mi < 5; mi++) {
            float av = adjT[w + mi * 8][j];
            acc[mi][0] = fmaf(av, mv0, acc[mi][0]);
            acc[mi][1] = fmaf(av, mv1, acc[mi][1]);
        }
    }
#pragma unroll
    for (int mi = 0; mi < 5; mi++) {
        int m = w + mi * 8;
        if (m < N_) {
#pragma unroll
            for (int h = 0; h < 2; h++) {
                float v = acc[mi][h];
                g_h1[((size_t)(b * N_ + m)) * 256 + c + h * 32] = v;
                float s = v, qq = v * v;
#pragma unroll
                for (int o = 16; o; o >>= 1) {
                    s  += __shfl_xor_sync(~0u, s, o);
                    qq += __shfl_xor_sync(~0u, qq, o);
                }
                if (lane == 0) { atomicAdd(&g_sum[1][m], s); atomicAdd(&g_ssq[1][m], qq); }
            }
        }
    }
}

// ---------------- launch ----------------
extern "C" void kernel_launch(void* const* d_in, const int* in_sizes, int n_in,
                              void* d_out, int out_size)
{
    const float* adj  = (const float*)d_in[0];
    const float* x    = (const float*)d_in[1];
    const float* cWs0 = (const float*)d_in[2];
    const float* cbs0 = (const float*)d_in[3];
    const float* cWe0 = (const float*)d_in[4];
    const float* cbe0 = (const float*)d_in[5];
    const float* cg0  = (const float*)d_in[6];
    const float* cb0  = (const float*)d_in[7];
    const float* cWs1 = (const float*)d_in[8];
    const float* cbs1 = (const float*)d_in[9];
    const float* cWe1 = (const float*)d_in[10];
    const float* cbe1 = (const float*)d_in[11];
    const float* cg1  = (const float*)d_in[12];
    const float* cb1  = (const float*)d_in[13];
    const float* lW0  = (const float*)d_in[14];
    const float* lb0  = (const float*)d_in[15];
    const float* lg0  = (const float*)d_in[16];
    const float* lbb0 = (const float*)d_in[17];
    const float* fW   = (const float*)d_in[18];
    const float* fb   = (const float*)d_in[19];
    float* out    = (float*)d_out;
    float* logdet = out + (size_t)B_ * N_ * DIN_;

    cudaFuncSetAttribute(k_einsum1, cudaFuncAttributeMaxDynamicSharedMemorySize, 65536);
    const int einsum_smem = (40 * 153 + NE_ * 66) * 4;

    k_zero<<<8, 256>>>(logdet);
    k_prep<<<128, 256>>>(cWs0, cWe0, cbe0, fW);
    k_feat<<<B_, 256>>>(adj, x);
    k_mma<0><<<dim3(2, 608), 256>>>(nullptr, nullptr, cbs0, nullptr, nullptr, nullptr, nullptr);
    k_stats0<<<ROWS_ / 8, 256>>>();
    k_finalize<<<1, 64>>>(cg0, cb0, 1.f / ((float)B_ * H0_), 0);
    k_mma<1><<<dim3(10, 608), 256>>>(cWs1, cWe1, cbs1, cbe1, nullptr, nullptr, nullptr);
    k_einsum1<<<dim3(B_, 4), 256, einsum_smem>>>(adj);
    k_finalize<<<1, 64>>>(cg1, cb1, 1.f / ((float)B_ * H1_), 1);
    k_mma<2><<<dim3(4, 16, N_), 256>>>(lW0, nullptr, lb0, nullptr, nullptr, nullptr, nullptr);
    k_finalize<<<1, 64>>>(lg0, lbb0, 1.f / ((float)B_ * L0_), 2);
    k_mma<3><<<dim3(1, 608), 256>>>(nullptr, nullptr, fb, nullptr, x, out, logdet);
}

// round 11
// speedup vs baseline: 2.9768x; 1.4349x over previous
#include <cuda_runtime.h>
#include <cuda_fp16.h>
#include <cstdint>

#define B_    2048
#define N_    38
#define E_    4
#define DIN_  9
#define L0_   512
#define NE_   152
#define ROWS_ 77824

#define NS    3            // cp.async stages
#define BROW  136          // half2 stride of As2/Bs rows (conflict-free)
#define TSZ   (16*BROW)    // half2 per k32 stage tile
#define ARST  (128*36)     // floats per raw-A stage

// ---------------- device scratch ----------------
__device__ float g_h0 [(size_t)ROWS_ * 256];
__device__ float g_hs1[(size_t)ROWS_ * 256];
__device__ float g_m1 [(size_t)ROWS_ * 1024];
__device__ float g_h1 [(size_t)ROWS_ * 256];
__device__ float g_h2 [(size_t)ROWS_ * 512];
__device__ __half2 g_FT  [(size_t)32 * ROWS_];     // layer0 A, k-major fp16
__device__ __half2 g_W0cT[32 * 256];
__device__ __half2 g_W1T [(size_t)128 * 1280];
__device__ __half2 g_lW0T[(size_t)128 * 512];
__device__ __half2 g_fWT [256 * 32];
__device__ float g_sum[3][N_], g_ssq[3][N_], g_scale[3][N_], g_shift[3][N_];

// ---------------- helpers ----------------
__device__ __forceinline__ uint32_t smem_u32(const void* p) {
    uint32_t a;
    asm("{ .reg .u64 t; cvta.to.shared.u64 t, %1; cvt.u32.u64 %0, t; }" : "=r"(a) : "l"(p));
    return a;
}
__device__ __forceinline__ void cpa16(uint32_t dst, const void* src) {
    asm volatile("cp.async.ca.shared.global [%0], [%1], 16;" :: "r"(dst), "l"(src));
}
__device__ __forceinline__ void cpa_commit() { asm volatile("cp.async.commit_group;"); }
template<int W> __device__ __forceinline__ void cpa_wait() {
    asm volatile("cp.async.wait_group %0;" :: "n"(W));
}
__device__ __forceinline__ void mma16(float* c, const uint32_t* a, const uint32_t* b) {
    asm volatile(
        "mma.sync.aligned.m16n8k16.row.col.f32.f16.f16.f32 "
        "{%0,%1,%2,%3},{%4,%5,%6,%7},{%8,%9},{%0,%1,%2,%3};"
        : "+f"(c[0]), "+f"(c[1]), "+f"(c[2]), "+f"(c[3])
        : "r"(a[0]), "r"(a[1]), "r"(a[2]), "r"(a[3]), "r"(b[0]), "r"(b[1]));
}

// ---------------- zero stats + logdet ----------------
__global__ void k_zero(float* __restrict__ logdet) {
    int i = blockIdx.x * 256 + threadIdx.x;
    if (i < 3 * N_) { (&g_sum[0][0])[i] = 0.f; (&g_ssq[0][0])[i] = 0.f; }
    if (i < B_) logdet[i] = 0.f;
}

// ---------------- prep: transpose + fp16-convert all weights ----------------
__global__ void k_prep(const float* __restrict__ Ws0, const float* __restrict__ We0,
                       const float* __restrict__ be0, const float* __restrict__ Ws1,
                       const float* __restrict__ We1, const float* __restrict__ lW0,
                       const float* __restrict__ fW)
{
    int i = blockIdx.x * 256 + threadIdx.x;
    if (i < 8192) {                                     // W0cT [32 k2][256 n]
        int k2 = i >> 8, n = i & 255;
        float v[2];
#pragma unroll
        for (int h = 0; h < 2; h++) {
            int k = 2 * k2 + h;
            float t = 0.f;
            if (k < 36)      { int e = k / 9; t = We0[(n * 4 + e) * 9 + (k - e * 9)]; }
            else if (k < 45) t = Ws0[n * 9 + k - 36];
            else if (k < 49) t = be0[n * 4 + k - 45];
            v[h] = t;
        }
        g_W0cT[i] = __floats2half2_rn(v[0], v[1]);
    } else if (i < 8192 + 163840) {                     // W1T [128][1280]
        int j = i - 8192, k2 = j / 1280, n = j % 1280;
        const float* r = (n < 256) ? (Ws1 + (size_t)n * 256) : (We1 + (size_t)(n - 256) * 256);
        g_W1T[j] = __floats2half2_rn(r[2 * k2], r[2 * k2 + 1]);
    } else if (i < 8192 + 163840 + 65536) {             // lW0T [128][512]
        int j = i - 8192 - 163840, k2 = j / 512, n = j % 512;
        g_lW0T[j] = __floats2half2_rn(lW0[(size_t)n * 256 + 2 * k2], lW0[(size_t)n * 256 + 2 * k2 + 1]);
    } else if (i < 8192 + 163840 + 65536 + 8192) {      // fWT [256][32]
        int j = i - 8192 - 163840 - 65536, k2 = j / 32, n = j % 32;
        float a = 0.f, b = 0.f;
        if (n < 18) { a = fW[(size_t)n * 512 + 2 * k2]; b = fW[(size_t)n * 512 + 2 * k2 + 1]; }
        g_fWT[j] = __floats2half2_rn(a, b);
    }
}

// ---------------- layer0 features -> g_FT (k-major fp16) ----------------
__global__ __launch_bounds__(256) void k_feat(const float* __restrict__ adj,
                                              const float* __restrict__ x)
{
    __shared__ float adjS[NE_][40];
    __shared__ float xsS[N_][9];
    __shared__ float Fs[N_][64];
    const int b = blockIdx.x, tid = threadIdx.x;
    const float* adjb = adj + (size_t)b * (E_ * N_ * N_);
    for (int i = tid; i < E_ * N_ * N_; i += 256) adjS[i / N_][i % N_] = adjb[i];
    for (int i = tid; i < N_ * 9; i += 256) {
        int n = i / 9, k = i - n * 9;
        xsS[n][k] = (n & 1) ? x[(b * N_ + n) * 9 + k] : 0.f;
    }
    __syncthreads();
    for (int i = tid; i < N_ * 64; i += 256) {
        int m = i >> 6, c = i & 63;
        float v = 0.f;
        if (c < 36) {
            int e = c / 9, k = c - e * 9;
            const float* ar = adjS[e * N_ + m];
#pragma unroll
            for (int n = 0; n < N_; n++) v = fmaf(ar[n], xsS[n][k], v);
        } else if (c < 45) v = xsS[m][c - 36];
        else if (c < 49) {
            const float* ar = adjS[(c - 45) * N_ + m];
#pragma unroll
            for (int n = 0; n < N_; n++) v += ar[n];
        }
        Fs[m][c] = v;
    }
    __syncthreads();
    for (int i = tid; i < 32 * N_; i += 256) {
        int k2 = i / N_, m = i - k2 * N_;
        g_FT[(size_t)k2 * ROWS_ + b * N_ + m] = __floats2half2_rn(Fs[m][2 * k2], Fs[m][2 * k2 + 1]);
    }
}

// ---------------- unified pipelined fp16 MMA GEMM ----------------
// MODE 0: h0 = FT @ W0cT + bs0, + stats0              grid(2, 608)   NT=128 K=64  (preconv)
// MODE 1: [hs1|m1] = bnrelu0(h0) @ W1T + bias         grid(10, 608)  NT=128 K=256
// MODE 2: h2 = bnrelu1(h1[:,nn,:]) @ lW0T + lb0+stats grid(4,16,38)  NT=128 K=256
// MODE 3: f = bnrelu2(h2) @ fWT + fb; coupling+logdet grid(1, 608)   NT=32  K=512
template<int MODE>
__global__ __launch_bounds__(256, 2) void k_mma(
    const float* __restrict__ bias, const float* __restrict__ bias2,
    const float* __restrict__ x, float* __restrict__ out, float* __restrict__ logdet)
{
    constexpr int  KTOT = (MODE == 0) ? 64 : (MODE == 3) ? 512 : 256;
    constexpr int  T    = KTOT / 32;
    constexpr int  NT   = (MODE == 3) ? 32 : 128;
    constexpr int  MT   = (NT == 128) ? 4 : 1;
    constexpr bool PRE  = (MODE == 0);
    constexpr int  LAYER = (MODE == 1) ? 0 : (MODE == 2) ? 1 : 2;
    constexpr int  CH   = NT / 4;    // 16B (4-half2) chunks per B k2-row

    extern __shared__ char dyn[];
    float*   Ar  = (float*)dyn;
    __half2* Bs  = (__half2*)(dyn + (PRE ? NS * TSZ * 4 : NS * ARST * 4));
    __half2* As2 = PRE ? (__half2*)dyn
                       : (__half2*)(dyn + NS * ARST * 4 + NS * TSZ * 4);
    float*   dump = (float*)dyn;    // mode3 epilogue alias
    __shared__ float sbuf[2][40];
    __shared__ float red[16];

    const int tid = threadIdx.x, lane = tid & 31, wid = tid >> 5;
    const int g = lane >> 2, tig = lane & 3;
    const int cb = blockIdx.x * NT;
    const int rb = blockIdx.y * 128;
    const int nn = (MODE == 2) ? blockIdx.z : 0;
    const int WROW = (NT == 128) ? (wid & 1) * 64 : wid * 16;
    const int WCOL = (NT == 128) ? (wid >> 1) * 32 : 0;
    const uint32_t arU  = smem_u32(Ar);
    const uint32_t bsU  = smem_u32(Bs);
    const uint32_t as2U = smem_u32(As2);

    const __half2* BT; int ldB;
    if      (MODE == 0) { BT = g_W0cT; ldB = 256;  }
    else if (MODE == 1) { BT = g_W1T;  ldB = 1280; }
    else if (MODE == 2) { BT = g_lW0T; ldB = 512;  }
    else                { BT = g_fWT;  ldB = 32;   }

    // A raw-row pointers for cp.async + BN consts for the convert pass
    const float* rowp[4];
    float csc = 1.f, csh = 0.f;
    const int cm = tid >> 1, ckh = tid & 1;
    const int j4 = (tid & 7) * 4;
    if (!PRE) {
#pragma unroll
        for (int i = 0; i < 4; i++) {
            int m = (tid >> 3) + 32 * i, gr = rb + m;
            if      (MODE == 1) rowp[i] = g_h0 + (size_t)gr * 256;
            else if (MODE == 2) rowp[i] = g_h1 + ((size_t)gr * N_ + nn) * 256;
            else                rowp[i] = g_h2 + (size_t)gr * 512;
        }
        int grc = rb + cm;
        int n = (MODE == 2) ? nn : (grc % N_);
        csc = g_scale[LAYER][n]; csh = g_shift[LAYER][n];
    }

    auto issue_nc = [&](int s) {
        const int sb = s % NS;
        const int kt = s * 32;
        // B tile: 16 k2-rows x NT half2; 16B chunk = 4 half2
        for (int c = tid; c < 16 * CH; c += 256) {
            int r = c / CH, j = c % CH;
            cpa16(bsU + (uint32_t)(sb * TSZ + r * BROW + j * 4) * 4,
                  BT + (size_t)(kt / 2 + r) * ldB + cb + j * 4);
        }
        if (PRE) {
            // A tile (preconverted): 16 k2-rows x 128 half2 = 32 chunks/row
            for (int c = tid; c < 16 * 32; c += 256) {
                int r = c >> 5, j = c & 31;
                cpa16(as2U + (uint32_t)(sb * TSZ + r * BROW + j * 4) * 4,
                      g_FT + (size_t)(kt / 2 + r) * ROWS_ + rb + j * 4);
            }
        } else {
#pragma unroll
            for (int i = 0; i < 4; i++) {
                int m = (tid >> 3) + 32 * i;
                cpa16(arU + (uint32_t)(sb * ARST + m * 36 + j4) * 4, rowp[i] + kt + j4);
            }
        }
    };

    float acc[MT][4][4];
#pragma unroll
    for (int a = 0; a < MT; a++)
#pragma unroll
        for (int b2 = 0; b2 < 4; b2++)
#pragma unroll
            for (int c2 = 0; c2 < 4; c2++) acc[a][b2][c2] = 0.f;

    // prologue
#pragma unroll
    for (int s = 0; s < NS - 1; s++) { if (s < T) issue_nc(s); cpa_commit(); }

    for (int t = 0; t < T; t++) {
        const int sb = t % NS;
        cpa_wait<NS - 2>();
        __syncthreads();
        if (!PRE) {
            // convert: raw fp32 [m][k] -> BN+ReLU -> half2 [k2][m]
            const float* src = Ar + sb * ARST + cm * 36 + ckh * 16;
            float f[16];
#pragma unroll
            for (int j = 0; j < 4; j++) {
                float4 v = *(const float4*)(src + j * 4);
                f[4 * j] = v.x; f[4 * j + 1] = v.y; f[4 * j + 2] = v.z; f[4 * j + 3] = v.w;
            }
#pragma unroll
            for (int j = 0; j < 16; j++) f[j] = fmaxf(fmaf(f[j], csc, csh), 0.f);
            __half2* d = As2 + (t & 1) * TSZ + ckh * 8 * BROW + cm;
#pragma unroll
            for (int j = 0; j < 8; j++) d[j * BROW] = __floats2half2_rn(f[2 * j], f[2 * j + 1]);
        }
        { int s2 = t + NS - 1; if (s2 < T) issue_nc(s2); cpa_commit(); }
        __syncthreads();
        // mma over the k32 tile
        const __half2* Ap2 = As2 + (PRE ? sb : (t & 1)) * TSZ;
        const __half2* Bp2 = Bs + sb * TSZ;
#pragma unroll
        for (int kk = 0; kk < 2; kk++) {
            uint32_t af[MT][4], bf[4][2];
#pragma unroll
            for (int mt = 0; mt < MT; mt++) {
                const int m0 = WROW + mt * 16 + g;
                af[mt][0] = *(const uint32_t*)&Ap2[(kk * 8 + tig) * BROW + m0];
                af[mt][1] = *(const uint32_t*)&Ap2[(kk * 8 + tig) * BROW + m0 + 8];
                af[mt][2] = *(const uint32_t*)&Ap2[(kk * 8 + tig + 4) * BROW + m0];
                af[mt][3] = *(const uint32_t*)&Ap2[(kk * 8 + tig + 4) * BROW + m0 + 8];
            }
#pragma unroll
            for (int nt = 0; nt < 4; nt++) {
                const int n0 = WCOL + nt * 8 + g;
                bf[nt][0] = *(const uint32_t*)&Bp2[(kk * 8 + tig) * BROW + n0];
                bf[nt][1] = *(const uint32_t*)&Bp2[(kk * 8 + tig + 4) * BROW + n0];
            }
#pragma unroll
            for (int mt = 0; mt < MT; mt++)
#pragma unroll
                for (int nt = 0; nt < 4; nt++)
                    mma16(acc[mt][nt], af[mt], bf[nt]);
        }
    }
    __syncthreads();

    // ---- epilogues ----
    if (MODE == 3) {
#pragma unroll
        for (int nt = 0; nt < 4; nt++) {
            const int c = nt * 8 + tig * 2;
            dump[(WROW + g) * 33 + c]         = acc[0][nt][0];
            dump[(WROW + g) * 33 + c + 1]     = acc[0][nt][1];
            dump[(WROW + g + 8) * 33 + c]     = acc[0][nt][2];
            dump[(WROW + g + 8) * 33 + c + 1] = acc[0][nt][3];
        }
        __syncthreads();
        const int row = tid >> 1, part = tid & 1;
        const int grow = rb + row;
        const int b = grow / N_, n = grow % N_;
        const int d0 = part * 5, d1 = part ? 9 : 5;
        float lds = 0.f;
        for (int d = d0; d < d1; d++) {
            float sl = dump[row * 33 + d] + bias[d];
            float tv = dump[row * 33 + 9 + d] + bias[9 + d];
            float sg = 1.f / (1.f + __expf(-sl));
            float xv = x[(size_t)grow * DIN_ + d];
            out[(size_t)grow * DIN_ + d] = (n & 1) ? xv : (xv + tv) * sg;
            lds += fminf(sl, 0.f) - log1pf(__expf(-fabsf(sl)));
        }
        atomicAdd(&logdet[b], lds);
        return;
    }

    if (MODE == 0) {
        if (tid < 40) { sbuf[0][tid] = 0.f; sbuf[1][tid] = 0.f; }
        __syncthreads();
    }
    float s_acc = 0.f, q_acc = 0.f;
#pragma unroll
    for (int mt = 0; mt < MT; mt++) {
        const int rloc = WROW + mt * 16 + g;
        float s0 = 0.f, q0 = 0.f, s1 = 0.f, q1 = 0.f;
#pragma unroll
        for (int nt = 0; nt < 4; nt++) {
            const int col = cb + WCOL + nt * 8 + tig * 2;
            float b0, b1;
            if (MODE == 1 && cb >= 256) { b0 = bias2[col - 256]; b1 = bias2[col - 255]; }
            else                        { b0 = bias[col];        b1 = bias[col + 1];    }
            float2 v0 = make_float2(acc[mt][nt][0] + b0, acc[mt][nt][1] + b1);
            float2 v1 = make_float2(acc[mt][nt][2] + b0, acc[mt][nt][3] + b1);
            s0 += v0.x + v0.y; q0 += v0.x * v0.x + v0.y * v0.y;
            s1 += v1.x + v1.y; q1 += v1.x * v1.x + v1.y * v1.y;
            const int row = rb + rloc;
            if (MODE == 0) {
                *(float2*)&g_h0[(size_t)row * 256 + col]       = v0;
                *(float2*)&g_h0[(size_t)(row + 8) * 256 + col] = v1;
            } else if (MODE == 1) {
                if (cb < 256) {
                    *(float2*)&g_hs1[(size_t)row * 256 + col]       = v0;
                    *(float2*)&g_hs1[(size_t)(row + 8) * 256 + col] = v1;
                } else {
                    *(float2*)&g_m1[(size_t)row * 1024 + col - 256]       = v0;
                    *(float2*)&g_m1[(size_t)(row + 8) * 1024 + col - 256] = v1;
                }
            } else {
                *(float2*)&g_h2[((size_t)row * N_ + nn) * 512 + col]       = v0;
                *(float2*)&g_h2[((size_t)(row + 8) * N_ + nn) * 512 + col] = v1;
            }
        }
        if (MODE == 0) {
            atomicAdd(&sbuf[0][(rb + rloc) % N_], s0);
            atomicAdd(&sbuf[1][(rb + rloc) % N_], q0);
            atomicAdd(&sbuf[0][(rb + rloc + 8) % N_], s1);
            atomicAdd(&sbuf[1][(rb + rloc + 8) % N_], q1);
        } else if (MODE == 2) {
            s_acc += s0 + s1; q_acc += q0 + q1;
        }
    }
    if (MODE == 0) {
        __syncthreads();
        if (tid < N_) {
            atomicAdd(&g_sum[0][tid], sbuf[0][tid]);
            atomicAdd(&g_ssq[0][tid], sbuf[1][tid]);
        }
    }
    if (MODE == 2) {
#pragma unroll
        for (int o = 16; o; o >>= 1) {
            s_acc += __shfl_xor_sync(~0u, s_acc, o);
            q_acc += __shfl_xor_sync(~0u, q_acc, o);
        }
        if (lane == 0) { red[wid] = s_acc; red[wid + 8] = q_acc; }
        __syncthreads();
        if (tid == 0) {
            float S = 0.f, Q = 0.f;
#pragma unroll
            for (int i = 0; i < 8; i++) { S += red[i]; Q += red[i + 8]; }
            atomicAdd(&g_sum[2][nn], S);
            atomicAdd(&g_ssq[2][nn], Q);
        }
    }
}

// ---------------- BN stat finalize ----------------
__global__ void k_finalize(const float* __restrict__ gg, const float* __restrict__ bb,
                           float inv_count, int layer)
{
    int t = threadIdx.x;
    if (t < N_) {
        float mu  = g_sum[layer][t] * inv_count;
        float var = g_ssq[layer][t] * inv_count - mu * mu;
        float scv = gg[t] * rsqrtf(var + 1e-5f);
        g_scale[layer][t] = scv;
        g_shift[layer][t] = bb[t] - mu * scv;
    }
}

// ---------------- layer 1 einsum (unchanged, proven) ----------------
__global__ __launch_bounds__(256) void k_einsum1(const float* __restrict__ adj)
{
    extern __shared__ float smr[];
    float (*adjT)[153] = (float(*)[153])smr;
    float (*Ms)[66]    = (float(*)[66])(smr + 40 * 153);
    const int b = blockIdx.x, cc = blockIdx.y * 64, tid = threadIdx.x;

    const float* adjb = adj + (size_t)b * (E_ * N_ * N_);
    for (int i = tid; i < E_ * N_ * N_; i += 256) {
        int e = i / (N_ * N_); int r = i % (N_ * N_);
        adjT[r / N_][e * N_ + (r % N_)] = adjb[i];
    }
    for (int i = tid; i < N_ * 64; i += 256) {
        int n = i >> 6, col = i & 63;
        float4 v = *(const float4*)&g_m1[((size_t)(b * N_ + n)) * 1024 + (size_t)(cc + col) * 4];
        Ms[n][col] = v.x; Ms[N_ + n][col] = v.y; Ms[2 * N_ + n][col] = v.z; Ms[3 * N_ + n][col] = v.w;
    }
    __syncthreads();

    const int w = tid >> 5, lane = tid & 31;
    const int c = cc + lane;
    float acc[5][2];
#pragma unroll
    for (int mi = 0; mi < 5; mi++) {
        int m = w + mi * 8;
        if (m < N_) {
            acc[mi][0] = g_hs1[((size_t)(b * N_ + m)) * 256 + c];
            acc[mi][1] = g_hs1[((size_t)(b * N_ + m)) * 256 + c + 32];
        } else acc[mi][0] = acc[mi][1] = 0.f;
    }
    for (int j = 0; j < NE_; j++) {
        float mv0 = Ms[j][lane], mv1 = Ms[j][lane + 32];
#pragma unroll
        for (int mi = 0; mi < 5; mi++) {
            float av = adjT[w + mi * 8][j];
            acc[mi][0] = fmaf(av, mv0, acc[mi][0]);
            acc[mi][1] = fmaf(av, mv1, acc[mi][1]);
        }
    }
#pragma unroll
    for (int mi = 0; mi < 5; mi++) {
        int m = w + mi * 8;
        if (m < N_) {
#pragma unroll
            for (int h = 0; h < 2; h++) {
                float v = acc[mi][h];
                g_h1[((size_t)(b * N_ + m)) * 256 + c + h * 32] = v;
                float s = v, qq = v * v;
#pragma unroll
                for (int o = 16; o; o >>= 1) {
                    s  += __shfl_xor_sync(~0u, s, o);
                    qq += __shfl_xor_sync(~0u, qq, o);
                }
                if (lane == 0) { atomicAdd(&g_sum[1][m], s); atomicAdd(&g_ssq[1][m], qq); }
            }
        }
    }
}

// ---------------- launch ----------------
extern "C" void kernel_launch(void* const* d_in, const int* in_sizes, int n_in,
                              void* d_out, int out_size)
{
    const float* adj  = (const float*)d_in[0];
    const float* x    = (const float*)d_in[1];
    const float* cWs0 = (const float*)d_in[2];
    const float* cbs0 = (const float*)d_in[3];
    const float* cWe0 = (const float*)d_in[4];
    const float* cbe0 = (const float*)d_in[5];
    const float* cg0  = (const float*)d_in[6];
    const float* cb0  = (const float*)d_in[7];
    const float* cWs1 = (const float*)d_in[8];
    const float* cbs1 = (const float*)d_in[9];
    const float* cWe1 = (const float*)d_in[10];
    const float* cbe1 = (const float*)d_in[11];
    const float* cg1  = (const float*)d_in[12];
    const float* cb1  = (const float*)d_in[13];
    const float* lW0  = (const float*)d_in[14];
    const float* lb0  = (const float*)d_in[15];
    const float* lg0  = (const float*)d_in[16];
    const float* lbb0 = (const float*)d_in[17];
    const float* fW   = (const float*)d_in[18];
    const float* fb   = (const float*)d_in[19];
    float* out    = (float*)d_out;
    float* logdet = out + (size_t)B_ * N_ * DIN_;

    const int smemPre  = NS * TSZ * 4 * 2;                              // 52224
    const int smemConv = NS * ARST * 4 + NS * TSZ * 4 + 2 * TSZ * 4;    // 98816
    cudaFuncSetAttribute(k_mma<0>, cudaFuncAttributeMaxDynamicSharedMemorySize, smemPre);
    cudaFuncSetAttribute(k_mma<1>, cudaFuncAttributeMaxDynamicSharedMemorySize, smemConv);
    cudaFuncSetAttribute(k_mma<2>, cudaFuncAttributeMaxDynamicSharedMemorySize, smemConv);
    cudaFuncSetAttribute(k_mma<3>, cudaFuncAttributeMaxDynamicSharedMemorySize, smemConv);
    cudaFuncSetAttribute(k_einsum1, cudaFuncAttributeMaxDynamicSharedMemorySize, 65536);
    const int einsum_smem = (40 * 153 + NE_ * 66) * 4;

    k_zero<<<8, 256>>>(logdet);
    k_prep<<<960, 256>>>(cWs0, cWe0, cbe0, cWs1, cWe1, lW0, fW);
    k_feat<<<B_, 256>>>(adj, x);
    k_mma<0><<<dim3(2, 608), 256, smemPre>>>(cbs0, nullptr, nullptr, nullptr, nullptr);
    k_finalize<<<1, 64>>>(cg0, cb0, 1.f / ((float)B_ * 256), 0);
    k_mma<1><<<dim3(10, 608), 256, smemConv>>>(cbs1, cbe1, nullptr, nullptr, nullptr);
    k_einsum1<<<dim3(B_, 4), 256, einsum_smem>>>(adj);
    k_finalize<<<1, 64>>>(cg1, cb1, 1.f / ((float)B_ * 256), 1);
    k_mma<2><<<dim3(4, 16, N_), 256, smemConv>>>(lb0, nullptr, nullptr, nullptr, nullptr);
    k_finalize<<<1, 64>>>(lg0, lbb0, 1.f / ((float)B_ * 512), 2);
    k_mma<3><<<dim3(1, 608), 256, smemConv>>>(fb, nullptr, x, out, logdet);
}

// round 14
// speedup vs baseline: 3.0004x; 1.0079x over previous
#include <cuda_runtime.h>
#include <cuda_fp16.h>
#include <cstdint>

#define B_    2048
#define N_    38
#define E_    4
#define DIN_  9
#define L0_   512
#define NE_   152
#define ROWS_ 77824

#define NS    4              // cp.async stages
#define BROW  136            // half2 stride of A rows (and B rows at NT=128)
#define ASTG  (16*BROW)      // half2 per A k32 stage

// ---------------- device scratch ----------------
__device__ float g_h0 [(size_t)ROWS_ * 256];
__device__ float g_hs1[(size_t)ROWS_ * 256];
__device__ float g_m1 [(size_t)ROWS_ * 1024];
__device__ float g_h1 [(size_t)ROWS_ * 256];
__device__ float g_h2 [(size_t)ROWS_ * 512];
__device__ __align__(16) __half2 g_FT [(size_t)32 * ROWS_];   // layer0 A, k-major
__device__ __align__(16) __half2 g_A1 [(size_t)128 * ROWS_];  // bnrelu0(h0) k-major
__device__ __align__(16) __half2 g_A2 [(size_t)128 * ROWS_];  // bnrelu1(h1) k-major
__device__ __align__(16) __half2 g_A3 [(size_t)256 * ROWS_];  // bnrelu2(h2) k-major
__device__ __align__(16) __half2 g_W0cT[32 * 256];
__device__ __align__(16) __half2 g_W1T [(size_t)128 * 1280];
__device__ __align__(16) __half2 g_lW0T[(size_t)128 * 512];
__device__ __align__(16) __half2 g_fWT [256 * 32];
__device__ float g_sum[3][N_], g_ssq[3][N_], g_scale[3][N_], g_shift[3][N_];

// ---------------- helpers ----------------
__device__ __forceinline__ uint32_t smem_u32(const void* p) {
    uint32_t a;
    asm("{ .reg .u64 t; cvta.to.shared.u64 t, %1; cvt.u32.u64 %0, t; }" : "=r"(a) : "l"(p));
    return a;
}
__device__ __forceinline__ void cpa16(uint32_t dst, const void* src) {
    asm volatile("cp.async.ca.shared.global [%0], [%1], 16;" :: "r"(dst), "l"(src));
}
__device__ __forceinline__ void cpa_commit() { asm volatile("cp.async.commit_group;"); }
template<int W> __device__ __forceinline__ void cpa_wait() {
    asm volatile("cp.async.wait_group %0;" :: "n"(W));
}
__device__ __forceinline__ void mma16(float* c, const uint32_t* a, const uint32_t* b) {
    asm volatile(
        "mma.sync.aligned.m16n8k16.row.col.f32.f16.f16.f32 "
        "{%0,%1,%2,%3},{%4,%5,%6,%7},{%8,%9},{%0,%1,%2,%3};"
        : "+f"(c[0]), "+f"(c[1]), "+f"(c[2]), "+f"(c[3])
        : "r"(a[0]), "r"(a[1]), "r"(a[2]), "r"(a[3]), "r"(b[0]), "r"(b[1]));
}

// ---------------- zero stats + logdet ----------------
__global__ void k_zero(float* __restrict__ logdet) {
    int i = blockIdx.x * 256 + threadIdx.x;
    if (i < 3 * N_) { (&g_sum[0][0])[i] = 0.f; (&g_ssq[0][0])[i] = 0.f; }
    if (i < B_) logdet[i] = 0.f;
}

// ---------------- prep: transpose + fp16-convert all weights ----------------
__global__ void k_prep(const float* __restrict__ Ws0, const float* __restrict__ We0,
                       const float* __restrict__ be0, const float* __restrict__ Ws1,
                       const float* __restrict__ We1, const float* __restrict__ lW0,
                       const float* __restrict__ fW)
{
    int i = blockIdx.x * 256 + threadIdx.x;
    if (i < 8192) {                                     // W0cT [32 k2][256 n]
        int k2 = i >> 8, n = i & 255;
        float v[2];
#pragma unroll
        for (int h = 0; h < 2; h++) {
            int k = 2 * k2 + h;
            float t = 0.f;
            if (k < 36)      { int e = k / 9; t = We0[(n * 4 + e) * 9 + (k - e * 9)]; }
            else if (k < 45) t = Ws0[n * 9 + k - 36];
            else if (k < 49) t = be0[n * 4 + k - 45];
            v[h] = t;
        }
        g_W0cT[i] = __floats2half2_rn(v[0], v[1]);
    } else if (i < 8192 + 163840) {                     // W1T [128][1280]
        int j = i - 8192, k2 = j / 1280, n = j % 1280;
        const float* r = (n < 256) ? (Ws1 + (size_t)n * 256) : (We1 + (size_t)(n - 256) * 256);
        g_W1T[j] = __floats2half2_rn(r[2 * k2], r[2 * k2 + 1]);
    } else if (i < 8192 + 163840 + 65536) {             // lW0T [128][512]
        int j = i - 8192 - 163840, k2 = j / 512, n = j % 512;
        g_lW0T[j] = __floats2half2_rn(lW0[(size_t)n * 256 + 2 * k2], lW0[(size_t)n * 256 + 2 * k2 + 1]);
    } else if (i < 8192 + 163840 + 65536 + 8192) {      // fWT [256][32]
        int j = i - 8192 - 163840 - 65536, k2 = j / 32, n = j % 32;
        float a = 0.f, b = 0.f;
        if (n < 18) { a = fW[(size_t)n * 512 + 2 * k2]; b = fW[(size_t)n * 512 + 2 * k2 + 1]; }
        g_fWT[j] = __floats2half2_rn(a, b);
    }
}

// ---------------- layer0 features -> g_FT (k-major fp16) ----------------
__global__ __launch_bounds__(256) void k_feat(const float* __restrict__ adj,
                                              const float* __restrict__ x)
{
    __shared__ float adjS[NE_][40];
    __shared__ float xsS[N_][9];
    __shared__ float Fs[N_][64];
    const int b = blockIdx.x, tid = threadIdx.x;
    const float* adjb = adj + (size_t)b * (E_ * N_ * N_);
    for (int i = tid; i < E_ * N_ * N_; i += 256) adjS[i / N_][i % N_] = adjb[i];
    for (int i = tid; i < N_ * 9; i += 256) {
        int n = i / 9, k = i - n * 9;
        xsS[n][k] = (n & 1) ? x[(b * N_ + n) * 9 + k] : 0.f;
    }
    __syncthreads();
    for (int i = tid; i < N_ * 64; i += 256) {
        int m = i >> 6, c = i & 63;
        float v = 0.f;
        if (c < 36) {
            int e = c / 9, k = c - e * 9;
            const float* ar = adjS[e * N_ + m];
#pragma unroll
            for (int n = 0; n < N_; n++) v = fmaf(ar[n], xsS[n][k], v);
        } else if (c < 45) v = xsS[m][c - 36];
        else if (c < 49) {
            const float* ar = adjS[(c - 45) * N_ + m];
#pragma unroll
            for (int n = 0; n < N_; n++) v += ar[n];
        }
        Fs[m][c] = v;
    }
    __syncthreads();
    for (int i = tid; i < 32 * N_; i += 256) {
        int k2 = i / N_, m = i - k2 * N_;
        g_FT[(size_t)k2 * ROWS_ + b * N_ + m] = __floats2half2_rn(Fs[m][2 * k2], Fs[m][2 * k2 + 1]);
    }
}

// ---------------- BN+ReLU+fp16+transpose convert pass ----------------
// src [ROWS][C] fp32 -> dst [C/2][ROWS] half2 (k-major).
// Device symbols selected INSIDE device code (host cannot pass __device__ addrs).
template<int LAYER>
__global__ __launch_bounds__(256) void k_conv()
{
    constexpr int C = (LAYER == 2) ? 512 : 256;
    const float* __restrict__ src = (LAYER == 0) ? g_h0 : (LAYER == 1) ? g_h1 : g_h2;
    __half2* __restrict__ dst = (LAYER == 0) ? g_A1 : (LAYER == 1) ? g_A2 : g_A3;

    __shared__ float ts[64][66];
    const int tid = threadIdx.x;
    const int rb = blockIdx.x * 64;
    const int cb = blockIdx.y * 64;      // float column base
    const int row = tid >> 2, ch = (tid & 3) * 16;
    {
        const int n = (rb + row) % N_;
        const float sc = g_scale[LAYER][n], sh = g_shift[LAYER][n];
        const float* sp = src + (size_t)(rb + row) * C + cb + ch;
#pragma unroll
        for (int j = 0; j < 4; j++) {
            float4 v = *(const float4*)(sp + j * 4);
            ts[row][ch + j * 4 + 0] = fmaxf(fmaf(v.x, sc, sh), 0.f);
            ts[row][ch + j * 4 + 1] = fmaxf(fmaf(v.y, sc, sh), 0.f);
            ts[row][ch + j * 4 + 2] = fmaxf(fmaf(v.z, sc, sh), 0.f);
            ts[row][ch + j * 4 + 3] = fmaxf(fmaf(v.w, sc, sh), 0.f);
        }
    }
    __syncthreads();
    const int wr = tid & 63, c2b = tid >> 6;
#pragma unroll
    for (int p = 0; p < 8; p++) {
        const int c2 = c2b + p * 4;
        float2 v = *(const float2*)&ts[wr][2 * c2];
        dst[(size_t)(cb / 2 + c2) * ROWS_ + rb + wr] = __floats2half2_rn(v.x, v.y);
    }
}

// ---------------- unified PRE fp16 MMA GEMM (pure cp.async -> mma) ----------------
// MODE 0: h0 = FT @ W0cT + bs0, +stats0              grid(2, 608)   K=64
// MODE 1: [hs1|m1] = A1 @ W1T + bias                 grid(10, 608)  K=256
// MODE 2: h2 = A2 @ lW0T + lb0, +stats2              grid(4, 608)   K=256
// MODE 3: f = A3 @ fWT + fb; coupling+logdet         grid(1, 608)   K=512, NT=32
template<int MODE>
__global__ __launch_bounds__(256, 2) void k_gemm(
    const float* __restrict__ bias, const float* __restrict__ bias2,
    const float* __restrict__ x, float* __restrict__ out, float* __restrict__ logdet)
{
    constexpr int K2   = (MODE == 0) ? 32 : (MODE == 3) ? 256 : 128;
    constexpr int T    = K2 / 16;
    constexpr int NT   = (MODE == 3) ? 32 : 128;
    constexpr int MT   = (NT == 128) ? 4 : 1;
    constexpr int BB   = (NT == 128) ? 136 : 40;   // B row stride (half2)
    constexpr int BSTG = 16 * BB;
    constexpr int STATL = (MODE == 0) ? 0 : (MODE == 2) ? 2 : -1;

    extern __shared__ char dyn[];
    __half2* Abuf = (__half2*)dyn;                       // [NS][ASTG]
    __half2* Bbuf = (__half2*)(dyn + NS * ASTG * 4);     // [NS][BSTG]
    float*   dump = (float*)dyn;                         // mode3 epilogue alias
    __shared__ float sbuf[2][40];

    const int tid = threadIdx.x, lane = tid & 31, wid = tid >> 5;
    const int g = lane >> 2, tig = lane & 3;
    const int cb = blockIdx.x * NT;
    const int rb = blockIdx.y * 128;
    const int WROW = (NT == 128) ? (wid & 1) * 64 : wid * 16;
    const int WCOL = (NT == 128) ? (wid >> 1) * 32 : 0;
    const uint32_t aU = smem_u32(Abuf);
    const uint32_t bU = smem_u32(Bbuf);

    const __half2* AT;
    if      (MODE == 0) AT = g_FT;
    else if (MODE == 1) AT = g_A1;
    else if (MODE == 2) AT = g_A2;
    else                AT = g_A3;
    const __half2* BT; int ldB;
    if      (MODE == 0) { BT = g_W0cT; ldB = 256;  }
    else if (MODE == 1) { BT = g_W1T;  ldB = 1280; }
    else if (MODE == 2) { BT = g_lW0T; ldB = 512;  }
    else                { BT = g_fWT;  ldB = 32;   }

    auto issue = [&](int s) {
        const int sb = s % NS;
        const int kr = s * 16;
        // A tile: 16 k2-rows x 128 half2 = 512 16B-chunks
        for (int c = tid; c < 512; c += 256) {
            int r = c >> 5, j = c & 31;
            cpa16(aU + (uint32_t)(sb * ASTG + r * BROW + j * 4) * 4,
                  AT + (size_t)(kr + r) * ROWS_ + rb + j * 4);
        }
        if (NT == 128) {
            for (int c = tid; c < 512; c += 256) {
                int r = c >> 5, j = c & 31;
                cpa16(bU + (uint32_t)(sb * BSTG + r * BB + j * 4) * 4,
                      BT + (size_t)(kr + r) * ldB + cb + j * 4);
            }
        } else {
            if (tid < 128) {
                int r = tid >> 3, j = tid & 7;
                cpa16(bU + (uint32_t)(sb * BSTG + r * BB + j * 4) * 4,
                      BT + (size_t)(kr + r) * ldB + cb + j * 4);
            }
        }
    };

    float acc[MT][4][4];
#pragma unroll
    for (int a = 0; a < MT; a++)
#pragma unroll
        for (int b2 = 0; b2 < 4; b2++)
#pragma unroll
            for (int c2 = 0; c2 < 4; c2++) acc[a][b2][c2] = 0.f;

    // prologue: NS-1 stages in flight
#pragma unroll
    for (int s = 0; s < NS - 1; s++) { if (s < T) issue(s); cpa_commit(); }

    for (int t = 0; t < T; t++) {
        const int sb = t % NS;
        cpa_wait<NS - 2>();
        __syncthreads();
        { int s2 = t + NS - 1; if (s2 < T) issue(s2); cpa_commit(); }
        const __half2* Ap2 = Abuf + sb * ASTG;
        const __half2* Bp2 = Bbuf + sb * BSTG;
#pragma unroll
        for (int kk = 0; kk < 2; kk++) {
            uint32_t af[MT][4], bf[4][2];
#pragma unroll
            for (int mt = 0; mt < MT; mt++) {
                const int m0 = WROW + mt * 16 + g;
                af[mt][0] = *(const uint32_t*)&Ap2[(kk * 8 + tig) * BROW + m0];
                af[mt][1] = *(const uint32_t*)&Ap2[(kk * 8 + tig) * BROW + m0 + 8];
                af[mt][2] = *(const uint32_t*)&Ap2[(kk * 8 + tig + 4) * BROW + m0];
                af[mt][3] = *(const uint32_t*)&Ap2[(kk * 8 + tig + 4) * BROW + m0 + 8];
            }
#pragma unroll
            for (int nt = 0; nt < 4; nt++) {
                const int n0 = WCOL + nt * 8 + g;
                bf[nt][0] = *(const uint32_t*)&Bp2[(kk * 8 + tig) * BB + n0];
                bf[nt][1] = *(const uint32_t*)&Bp2[(kk * 8 + tig + 4) * BB + n0];
            }
#pragma unroll
            for (int mt = 0; mt < MT; mt++)
#pragma unroll
                for (int nt = 0; nt < 4; nt++)
                    mma16(acc[mt][nt], af[mt], bf[nt]);
        }
    }
    __syncthreads();

    // ---- epilogues ----
    if (MODE == 3) {
#pragma unroll
        for (int nt = 0; nt < 4; nt++) {
            const int c = nt * 8 + tig * 2;
            dump[(WROW + g) * 33 + c]         = acc[0][nt][0];
            dump[(WROW + g) * 33 + c + 1]     = acc[0][nt][1];
            dump[(WROW + g + 8) * 33 + c]     = acc[0][nt][2];
            dump[(WROW + g + 8) * 33 + c + 1] = acc[0][nt][3];
        }
        __syncthreads();
        const int row = tid >> 1, part = tid & 1;
        const int grow = rb + row;
        const int b = grow / N_, n = grow % N_;
        const int d0 = part * 5, d1 = part ? 9 : 5;
        float lds = 0.f;
        for (int d = d0; d < d1; d++) {
            float sl = dump[row * 33 + d] + bias[d];
            float tv = dump[row * 33 + 9 + d] + bias[9 + d];
            float sg = 1.f / (1.f + __expf(-sl));
            float xv = x[(size_t)grow * DIN_ + d];
            out[(size_t)grow * DIN_ + d] = (n & 1) ? xv : (xv + tv) * sg;
            lds += fminf(sl, 0.f) - log1pf(__expf(-fabsf(sl)));
        }
        atomicAdd(&logdet[b], lds);
        return;
    }

    if (STATL >= 0) {
        if (tid < 40) { sbuf[0][tid] = 0.f; sbuf[1][tid] = 0.f; }
        __syncthreads();
    }
#pragma unroll
    for (int mt = 0; mt < MT; mt++) {
        const int rloc = WROW + mt * 16 + g;
        float s0 = 0.f, q0 = 0.f, s1 = 0.f, q1 = 0.f;
#pragma unroll
        for (int nt = 0; nt < 4; nt++) {
            const int col = cb + WCOL + nt * 8 + tig * 2;
            float b0, b1;
            if (MODE == 1 && cb >= 256) { b0 = bias2[col - 256]; b1 = bias2[col - 255]; }
            else                        { b0 = bias[col];        b1 = bias[col + 1];    }
            float2 v0 = make_float2(acc[mt][nt][0] + b0, acc[mt][nt][1] + b1);
            float2 v1 = make_float2(acc[mt][nt][2] + b0, acc[mt][nt][3] + b1);
            s0 += v0.x + v0.y; q0 += v0.x * v0.x + v0.y * v0.y;
            s1 += v1.x + v1.y; q1 += v1.x * v1.x + v1.y * v1.y;
            const int row = rb + rloc;
            if (MODE == 0) {
                *(float2*)&g_h0[(size_t)row * 256 + col]       = v0;
                *(float2*)&g_h0[(size_t)(row + 8) * 256 + col] = v1;
            } else if (MODE == 1) {
                if (cb < 256) {
                    *(float2*)&g_hs1[(size_t)row * 256 + col]       = v0;
                    *(float2*)&g_hs1[(size_t)(row + 8) * 256 + col] = v1;
                } else {
                    *(float2*)&g_m1[(size_t)row * 1024 + col - 256]       = v0;
                    *(float2*)&g_m1[(size_t)(row + 8) * 1024 + col - 256] = v1;
                }
            } else {
                *(float2*)&g_h2[(size_t)row * 512 + col]       = v0;
                *(float2*)&g_h2[(size_t)(row + 8) * 512 + col] = v1;
            }
        }
        if (STATL >= 0) {
            atomicAdd(&sbuf[0][(rb + rloc) % N_], s0);
            atomicAdd(&sbuf[1][(rb + rloc) % N_], q0);
            atomicAdd(&sbuf[0][(rb + rloc + 8) % N_], s1);
            atomicAdd(&sbuf[1][(rb + rloc + 8) % N_], q1);
        }
    }
    if (STATL >= 0) {
        __syncthreads();
        if (tid < N_) {
            atomicAdd(&g_sum[STATL][tid], sbuf[0][tid]);
            atomicAdd(&g_ssq[STATL][tid], sbuf[1][tid]);
        }
    }
}

// ---------------- BN stat finalize ----------------
__global__ void k_finalize(const float* __restrict__ gg, const float* __restrict__ bb,
                           float inv_count, int layer)
{
    int t = threadIdx.x;
    if (t < N_) {
        float mu  = g_sum[layer][t] * inv_count;
        float var = g_ssq[layer][t] * inv_count - mu * mu;
        float scv = gg[t] * rsqrtf(var + 1e-5f);
        g_scale[layer][t] = scv;
        g_shift[layer][t] = bb[t] - mu * scv;
    }
}

// ---------------- layer 1 einsum (unchanged, proven) ----------------
__global__ __launch_bounds__(256) void k_einsum1(const float* __restrict__ adj)
{
    extern __shared__ float smr[];
    float (*adjT)[153] = (float(*)[153])smr;
    float (*Ms)[66]    = (float(*)[66])(smr + 40 * 153);
    const int b = blockIdx.x, cc = blockIdx.y * 64, tid = threadIdx.x;

    const float* adjb = adj + (size_t)b * (E_ * N_ * N_);
    for (int i = tid; i < E_ * N_ * N_; i += 256) {
        int e = i / (N_ * N_); int r = i % (N_ * N_);
        adjT[r / N_][e * N_ + (r % N_)] = adjb[i];
    }
    for (int i = tid; i < N_ * 64; i += 256) {
        int n = i >> 6, col = i & 63;
        float4 v = *(const float4*)&g_m1[((size_t)(b * N_ + n)) * 1024 + (size_t)(cc + col) * 4];
        Ms[n][col] = v.x; Ms[N_ + n][col] = v.y; Ms[2 * N_ + n][col] = v.z; Ms[3 * N_ + n][col] = v.w;
    }
    __syncthreads();

    const int w = tid >> 5, lane = tid & 31;
    const int c = cc + lane;
    float acc[5][2];
#pragma unroll
    for (int mi = 0; mi < 5; mi++) {
        int m = w + mi * 8;
        if (m < N_) {
            acc[mi][0] = g_hs1[((size_t)(b * N_ + m)) * 256 + c];
            acc[mi][1] = g_hs1[((size_t)(b * N_ + m)) * 256 + c + 32];
        } else acc[mi][0] = acc[mi][1] = 0.f;
    }
    for (int j = 0; j < NE_; j++) {
        float mv0 = Ms[j][lane], mv1 = Ms[j][lane + 32];
#pragma unroll
        for (int mi = 0; mi < 5; mi++) {
            float av = adjT[w + mi * 8][j];
            acc[mi][0] = fmaf(av, mv0, acc[mi][0]);
            acc[mi][1] = fmaf(av, mv1, acc[mi][1]);
        }
    }
#pragma unroll
    for (int mi = 0; mi < 5; mi++) {
        int m = w + mi * 8;
        if (m < N_) {
#pragma unroll
            for (int h = 0; h < 2; h++) {
                float v = acc[mi][h];
                g_h1[((size_t)(b * N_ + m)) * 256 + c + h * 32] = v;
                float s = v, qq = v * v;
#pragma unroll
                for (int o = 16; o; o >>= 1) {
                    s  += __shfl_xor_sync(~0u, s, o);
                    qq += __shfl_xor_sync(~0u, qq, o);
                }
                if (lane == 0) { atomicAdd(&g_sum[1][m], s); atomicAdd(&g_ssq[1][m], qq); }
            }
        }
    }
}

// ---------------- launch ----------------
extern "C" void kernel_launch(void* const* d_in, const int* in_sizes, int n_in,
                              void* d_out, int out_size)
{
    const float* adj  = (const float*)d_in[0];
    const float* x    = (const float*)d_in[1];
    const float* cWs0 = (const float*)d_in[2];
    const float* cbs0 = (const float*)d_in[3];
    const float* cWe0 = (const float*)d_in[4];
    const float* cbe0 = (const float*)d_in[5];
    const float* cg0  = (const float*)d_in[6];
    const float* cb0  = (const float*)d_in[7];
    const float* cWs1 = (const float*)d_in[8];
    const float* cbs1 = (const float*)d_in[9];
    const float* cWe1 = (const float*)d_in[10];
    const float* cbe1 = (const float*)d_in[11];
    const float* cg1  = (const float*)d_in[12];
    const float* cb1  = (const float*)d_in[13];
    const float* lW0  = (const float*)d_in[14];
    const float* lb0  = (const float*)d_in[15];
    const float* lg0  = (const float*)d_in[16];
    const float* lbb0 = (const float*)d_in[17];
    const float* fW   = (const float*)d_in[18];
    const float* fb   = (const float*)d_in[19];
    float* out    = (float*)d_out;
    float* logdet = out + (size_t)B_ * N_ * DIN_;

    const int smem128 = NS * (ASTG + 16 * 136) * 4;   // 69632
    const int smem32  = NS * (ASTG + 16 * 40) * 4;    // 45056
    cudaFuncSetAttribute(k_gemm<0>, cudaFuncAttributeMaxDynamicSharedMemorySize, smem128);
    cudaFuncSetAttribute(k_gemm<1>, cudaFuncAttributeMaxDynamicSharedMemorySize, smem128);
    cudaFuncSetAttribute(k_gemm<2>, cudaFuncAttributeMaxDynamicSharedMemorySize, smem128);
    cudaFuncSetAttribute(k_gemm<3>, cudaFuncAttributeMaxDynamicSharedMemorySize, smem32);
    cudaFuncSetAttribute(k_einsum1, cudaFuncAttributeMaxDynamicSharedMemorySize, 65536);
    const int einsum_smem = (40 * 153 + NE_ * 66) * 4;

    k_zero<<<8, 256>>>(logdet);
    k_prep<<<960, 256>>>(cWs0, cWe0, cbe0, cWs1, cWe1, lW0, fW);
    k_feat<<<B_, 256>>>(adj, x);
    k_gemm<0><<<dim3(2, 608), 256, smem128>>>(cbs0, nullptr, nullptr, nullptr, nullptr);
    k_finalize<<<1, 64>>>(cg0, cb0, 1.f / ((float)B_ * 256), 0);
    k_conv<0><<<dim3(1216, 4), 256>>>();
    k_gemm<1><<<dim3(10, 608), 256, smem128>>>(cbs1, cbe1, nullptr, nullptr, nullptr);
    k_einsum1<<<dim3(B_, 4), 256, einsum_smem>>>(adj);
    k_finalize<<<1, 64>>>(cg1, cb1, 1.f / ((float)B_ * 256), 1);
    k_conv<1><<<dim3(1216, 4), 256>>>();
    k_gemm<2><<<dim3(4, 608), 256, smem128>>>(lb0, nullptr, nullptr, nullptr, nullptr);
    k_finalize<<<1, 64>>>(lg0, lbb0, 1.f / ((float)B_ * 512), 2);
    k_conv<2><<<dim3(1216, 8), 256>>>();
    k_gemm<3><<<dim3(1, 608), 256, smem32>>>(fb, nullptr, x, out, logdet);
}